// round 10
// baseline (speedup 1.0000x reference)
#include <cuda_runtime.h>
#include <math.h>

#define N_NODES 50000
#define N_EDGES 800000
#define C 64
#define OUTC 16
#define NG 196          // ceil(N_NODES/256)
#define E4G 782         // ceil(N_EDGES/4/256)
#define LTG 782         // ceil(N_NODES/64)
#define SM4G 3125       // N_NODES/16 (exact)
#define BN_EPS 1e-5f
typedef unsigned long long ull;

// ---- packed f32x2 helpers (sm_103a FFMA2) ----
#define FMA2(d, a, b, c) \
    asm("fma.rn.f32x2 %0, %1, %2, %3;" : "=l"(d) : "l"(a), "l"(b), "l"(c))
#define PACKF2(out, lo, hi) \
    asm("mov.b64 %0, {%1, %2};" : "=l"(out) : "r"(__float_as_uint(lo)), "r"(__float_as_uint(hi)))
#define UNPACKF2(lo, hi, in) \
    { unsigned int _l, _h; asm("mov.b64 {%0, %1}, %2;" : "=r"(_l), "=r"(_h) : "l"(in)); \
      lo = __uint_as_float(_l); hi = __uint_as_float(_h); }

// ---------------- device scratch ----------------
__device__ float g_bufA[N_NODES * C];     // agg (segment-min output)
__device__ float g_bufB[N_NODES * C];     // pre-BN linear output
__device__ float g_partS[LTG * C];
__device__ float g_partQ[LTG * C];
__device__ float g_bnp[2 * C];            // [scale | shift]
__device__ int   g_deg[N_NODES];
__device__ int   g_rowptr[N_NODES + 1];
__device__ int   g_cursor[N_NODES];
__device__ int   g_col[N_EDGES];
__device__ int   g_chunksum[256];
__device__ int   g_chunkoff[256];

// ---------------- CSR build ----------------
__global__ void zero_deg_kernel() {
    int i = blockIdx.x * 256 + threadIdx.x;
    if (i < N_NODES) g_deg[i] = 0;
}

// edge_index is int32 (JAX x64 disabled); 4 edges per thread via int4.
__global__ void hist_kernel(const int* __restrict__ ei) {
    int e4 = blockIdx.x * 256 + threadIdx.x;
    if (e4 < N_EDGES / 4) {
        int4 d = ((const int4*)(ei + N_EDGES))[e4];
        atomicAdd(&g_deg[d.x], 1);
        atomicAdd(&g_deg[d.y], 1);
        atomicAdd(&g_deg[d.z], 1);
        atomicAdd(&g_deg[d.w], 1);
    }
}

__global__ void chunk_sum_kernel() {
    __shared__ int sh[256];
    int b = blockIdx.x, t = threadIdx.x;
    int i = b * 256 + t;
    sh[t] = (i < N_NODES) ? g_deg[i] : 0;
    __syncthreads();
    for (int off = 128; off; off >>= 1) {
        if (t < off) sh[t] += sh[t + off];
        __syncthreads();
    }
    if (t == 0) g_chunksum[b] = sh[0];
}

__global__ void scan_chunks_kernel() {
    __shared__ int sh[256];
    int t = threadIdx.x;
    int v = (t < NG) ? g_chunksum[t] : 0;
    sh[t] = v;
    __syncthreads();
    for (int off = 1; off < 256; off <<= 1) {
        int add = (t >= off) ? sh[t - off] : 0;
        __syncthreads();
        sh[t] += add;
        __syncthreads();
    }
    if (t < NG) g_chunkoff[t] = sh[t] - v;
    if (t == 255) g_rowptr[N_NODES] = sh[255];
}

__global__ void scan_within_kernel() {
    __shared__ int sh[256];
    int b = blockIdx.x, t = threadIdx.x;
    int i = b * 256 + t;
    int v = (i < N_NODES) ? g_deg[i] : 0;
    sh[t] = v;
    __syncthreads();
    for (int off = 1; off < 256; off <<= 1) {
        int add = (t >= off) ? sh[t - off] : 0;
        __syncthreads();
        sh[t] += add;
        __syncthreads();
    }
    if (i < N_NODES) {
        int r = g_chunkoff[b] + sh[t] - v;
        g_rowptr[i] = r;
        g_cursor[i] = r;
    }
}

__global__ void scatter_kernel(const int* __restrict__ ei) {
    int e4 = blockIdx.x * 256 + threadIdx.x;
    if (e4 < N_EDGES / 4) {
        int4 s = ((const int4*)ei)[e4];
        int4 d = ((const int4*)(ei + N_EDGES))[e4];
        g_col[atomicAdd(&g_cursor[d.x], 1)] = s.x;
        g_col[atomicAdd(&g_cursor[d.y], 1)] = s.y;
        g_col[atomicAdd(&g_cursor[d.z], 1)] = s.z;
        g_col[atomicAdd(&g_cursor[d.w], 1)] = s.w;
    }
}

// ---------------- segment-min gather (float4, fused BN+ReLU on load) --------
// 16 lanes per node (4 channels each via float4); 16 nodes per 256-thread block.
// mode 0: gather raw xin rows. mode 1: gather relu(bn(g_bufB)) rows.
__global__ void seg_min_kernel(const float* __restrict__ xin, int mode) {
    int tid = threadIdx.x;
    int node = blockIdx.x * 16 + (tid >> 4);
    int c4 = tid & 15;
    const float4* src = (const float4*)(mode ? (const float*)g_bufB : xin);
    float4 sc, sh;
    if (mode) {
        sc = *(const float4*)&g_bnp[c4 * 4];
        sh = *(const float4*)&g_bnp[64 + c4 * 4];
    }
    int beg = g_rowptr[node];
    int end = g_rowptr[node + 1];
    const float INF = __int_as_float(0x7f800000);
    float4 m0 = {INF, INF, INF, INF}, m1 = m0, m2 = m0, m3 = m0;
    int e = beg;
    for (; e + 4 <= end; e += 4) {
        int s0 = g_col[e], s1 = g_col[e + 1], s2 = g_col[e + 2], s3 = g_col[e + 3];
        float4 v0 = src[s0 * 16 + c4];
        float4 v1 = src[s1 * 16 + c4];
        float4 v2 = src[s2 * 16 + c4];
        float4 v3 = src[s3 * 16 + c4];
        if (mode) {
            v0.x = fmaxf(v0.x * sc.x + sh.x, 0.f); v0.y = fmaxf(v0.y * sc.y + sh.y, 0.f);
            v0.z = fmaxf(v0.z * sc.z + sh.z, 0.f); v0.w = fmaxf(v0.w * sc.w + sh.w, 0.f);
            v1.x = fmaxf(v1.x * sc.x + sh.x, 0.f); v1.y = fmaxf(v1.y * sc.y + sh.y, 0.f);
            v1.z = fmaxf(v1.z * sc.z + sh.z, 0.f); v1.w = fmaxf(v1.w * sc.w + sh.w, 0.f);
            v2.x = fmaxf(v2.x * sc.x + sh.x, 0.f); v2.y = fmaxf(v2.y * sc.y + sh.y, 0.f);
            v2.z = fmaxf(v2.z * sc.z + sh.z, 0.f); v2.w = fmaxf(v2.w * sc.w + sh.w, 0.f);
            v3.x = fmaxf(v3.x * sc.x + sh.x, 0.f); v3.y = fmaxf(v3.y * sc.y + sh.y, 0.f);
            v3.z = fmaxf(v3.z * sc.z + sh.z, 0.f); v3.w = fmaxf(v3.w * sc.w + sh.w, 0.f);
        }
        m0.x = fminf(m0.x, v0.x); m0.y = fminf(m0.y, v0.y); m0.z = fminf(m0.z, v0.z); m0.w = fminf(m0.w, v0.w);
        m1.x = fminf(m1.x, v1.x); m1.y = fminf(m1.y, v1.y); m1.z = fminf(m1.z, v1.z); m1.w = fminf(m1.w, v1.w);
        m2.x = fminf(m2.x, v2.x); m2.y = fminf(m2.y, v2.y); m2.z = fminf(m2.z, v2.z); m2.w = fminf(m2.w, v2.w);
        m3.x = fminf(m3.x, v3.x); m3.y = fminf(m3.y, v3.y); m3.z = fminf(m3.z, v3.z); m3.w = fminf(m3.w, v3.w);
    }
    for (; e < end; e++) {
        float4 v = src[g_col[e] * 16 + c4];
        if (mode) {
            v.x = fmaxf(v.x * sc.x + sh.x, 0.f); v.y = fmaxf(v.y * sc.y + sh.y, 0.f);
            v.z = fmaxf(v.z * sc.z + sh.z, 0.f); v.w = fmaxf(v.w * sc.w + sh.w, 0.f);
        }
        m0.x = fminf(m0.x, v.x); m0.y = fminf(m0.y, v.y);
        m0.z = fminf(m0.z, v.z); m0.w = fminf(m0.w, v.w);
    }
    float4 m;
    m.x = fminf(fminf(m0.x, m1.x), fminf(m2.x, m3.x));
    m.y = fminf(fminf(m0.y, m1.y), fminf(m2.y, m3.y));
    m.z = fminf(fminf(m0.z, m1.z), fminf(m2.z, m3.z));
    m.w = fminf(fminf(m0.w, m1.w), fminf(m2.w, m3.w));
    if (beg >= end) m = make_float4(0.f, 0.f, 0.f, 0.f);
    ((float4*)g_bufA)[node * 16 + c4] = m;
}

// ---------------- fused dual-GEMM 64->64 via FFMA2 + BN partials -------------
// 256 threads, 64-node tile. Thread (cg=tid&15, slot=tid>>4) owns channel
// pairs {2cg,2cg+1} and {2cg+32,2cg+33} x nodes {slot, slot+16, slot+32, slot+48}.
#define MMA64() \
    _Pragma("unroll 4") \
    for (int ci = 0; ci < 64; ci++) { \
        ull bw0 = *(const ull*)&sW[ci * 64 + 2 * cg]; \
        ull bw1 = *(const ull*)&sW[ci * 64 + 2 * cg + 32]; \
        float x0 = sX[slot * 65 + ci]; \
        float x1 = sX[(slot + 16) * 65 + ci]; \
        float x2 = sX[(slot + 32) * 65 + ci]; \
        float x3 = sX[(slot + 48) * 65 + ci]; \
        ull a0, a1, a2, a3; \
        PACKF2(a0, x0, x0); PACKF2(a1, x1, x1); PACKF2(a2, x2, x2); PACKF2(a3, x3, x3); \
        FMA2(acc[0][0], a0, bw0, acc[0][0]); FMA2(acc[1][0], a0, bw1, acc[1][0]); \
        FMA2(acc[0][1], a1, bw0, acc[0][1]); FMA2(acc[1][1], a1, bw1, acc[1][1]); \
        FMA2(acc[0][2], a2, bw0, acc[0][2]); FMA2(acc[1][2], a2, bw1, acc[1][2]); \
        FMA2(acc[0][3], a3, bw0, acc[0][3]); FMA2(acc[1][3], a3, bw1, acc[1][3]); \
    }

__global__ void linear64_kernel(const float* __restrict__ xin, int use_bn,
                                const float* __restrict__ Wl,
                                const float* __restrict__ Wr,
                                const float* __restrict__ bias) {
    __shared__ __align__(16) float sW[64 * 64];
    __shared__ __align__(16) float sX[64 * 65];
    __shared__ float sRS[64 * 16];
    __shared__ float sRQ[64 * 16];

    const float* h2 = use_bn ? (const float*)g_bufB : xin;
    int tid = threadIdx.x;
    int base = blockIdx.x * 64;
    int cg = tid & 15, slot = tid >> 4;

    ull acc[2][4];
    {
        float2 bp0 = *(const float2*)&bias[2 * cg];
        float2 bp1 = *(const float2*)&bias[2 * cg + 32];
        ull b0, b1;
        PACKF2(b0, bp0.x, bp0.y);
        PACKF2(b1, bp1.x, bp1.y);
#pragma unroll
        for (int j = 0; j < 4; j++) { acc[0][j] = b0; acc[1][j] = b1; }
    }

    // ---- pass 1: Wl x agg ----
    for (int q = tid; q < 4096; q += 256) sW[q] = Wl[q];
    for (int q = tid; q < 4096; q += 256) {
        int nd = q >> 6, c = q & 63, gn = base + nd;
        sX[nd * 65 + c] = (gn < N_NODES) ? g_bufA[gn * C + c] : 0.0f;
    }
    __syncthreads();
    MMA64();
    __syncthreads();

    // ---- pass 2: Wr x h (BN+ReLU fused on load for layer >= 2) ----
    for (int q = tid; q < 4096; q += 256) sW[q] = Wr[q];
    for (int q = tid; q < 4096; q += 256) {
        int nd = q >> 6, c = q & 63, gn = base + nd;
        float v = (gn < N_NODES) ? h2[gn * C + c] : 0.0f;
        if (use_bn) v = fmaxf(v * g_bnp[c] + g_bnp[64 + c], 0.0f);
        sX[nd * 65 + c] = v;
    }
    __syncthreads();
    MMA64();

    // ---- epilogue: write output pairs + deterministic BN partials ----
#pragma unroll
    for (int p = 0; p < 2; p++) {
        int co0 = 2 * cg + 32 * p;
        float s1l = 0.f, s2l = 0.f, s1h = 0.f, s2h = 0.f;
#pragma unroll
        for (int j = 0; j < 4; j++) {
            int gn = base + slot + 16 * j;
            float lo, hi;
            UNPACKF2(lo, hi, acc[p][j]);
            if (gn < N_NODES) {
                *(float2*)&g_bufB[gn * C + co0] = make_float2(lo, hi);
                s1l += lo; s2l += lo * lo;
                s1h += hi; s2h += hi * hi;
            }
        }
        sRS[co0 * 16 + slot] = s1l;
        sRQ[co0 * 16 + slot] = s2l;
        sRS[(co0 + 1) * 16 + slot] = s1h;
        sRQ[(co0 + 1) * 16 + slot] = s2h;
    }
    __syncthreads();
    if (tid < 64) {
        float t1 = 0.0f, t2 = 0.0f;
#pragma unroll
        for (int s = 0; s < 16; s++) {
            t1 += sRS[tid * 16 + s];
            t2 += sRQ[tid * 16 + s];
        }
        g_partS[blockIdx.x * 64 + tid] = t1;
        g_partQ[blockIdx.x * 64 + tid] = t2;
    }
}

// ---------------- BN stats: deterministic reduce + scale/shift prep ---------
__global__ void bn_stats_kernel(const float* __restrict__ g, const float* __restrict__ be) {
    __shared__ float redS[256], redQ[256];
    int t = threadIdx.x;         // 256
    int c = t & 63, part = t >> 6;
    float s = 0.0f, q = 0.0f;
    for (int i = part; i < LTG; i += 4) {
        s += g_partS[i * 64 + c];
        q += g_partQ[i * 64 + c];
    }
    redS[t] = s;
    redQ[t] = q;
    __syncthreads();
    if (t < 64) {
        float S = redS[t] + redS[t + 64] + redS[t + 128] + redS[t + 192];
        float Q = redQ[t] + redQ[t + 64] + redQ[t + 128] + redQ[t + 192];
        float inv = 1.0f / (float)N_NODES;
        float mu = S * inv;
        float var = Q * inv - mu * mu;
        float sc = g[t] * rsqrtf(var + BN_EPS);
        g_bnp[t] = sc;
        g_bnp[64 + t] = be[t] - mu * sc;
    }
}

// ---------------- fused dual-GEMM 64->16 + log_softmax ----------------------
__global__ void linear16_ls_kernel(const float* __restrict__ Wl,
                                   const float* __restrict__ Wr,
                                   const float* __restrict__ b,
                                   float* __restrict__ out) {
    __shared__ float sWl[64 * 16], sWr[64 * 16];
    __shared__ float sA[64 * 65], sH[64 * 65];

    int tid = threadIdx.x;
    int base = blockIdx.x * 64;

    for (int q = tid; q < 1024; q += 256) { sWl[q] = Wl[q]; sWr[q] = Wr[q]; }
    for (int q = tid; q < 4096; q += 256) {
        int nd = q >> 6, c = q & 63, gn = base + nd;
        float a = 0.0f, hh = 0.0f;
        if (gn < N_NODES) {
            a = g_bufA[gn * C + c];
            hh = fmaxf(g_bufB[gn * C + c] * g_bnp[c] + g_bnp[64 + c], 0.0f);
        }
        sA[nd * 65 + c] = a;
        sH[nd * 65 + c] = hh;
    }
    __syncthreads();

    int c_out = tid & 15, nslot = tid >> 4;
    float acc[4];
    float bb = b[c_out];
#pragma unroll
    for (int j = 0; j < 4; j++) acc[j] = bb;

#pragma unroll 8
    for (int ci = 0; ci < 64; ci++) {
        float wl = sWl[ci * 16 + c_out];
        float wr = sWr[ci * 16 + c_out];
#pragma unroll
        for (int j = 0; j < 4; j++) {
            int nd = nslot + 16 * j;
            acc[j] += sA[nd * 65 + ci] * wl + sH[nd * 65 + ci] * wr;
        }
    }

#pragma unroll
    for (int j = 0; j < 4; j++) {
        int gn = base + nslot + 16 * j;
        float v = acc[j];
        float m = v;
#pragma unroll
        for (int off = 8; off; off >>= 1)
            m = fmaxf(m, __shfl_xor_sync(0xffffffffu, m, off));
        float e = expf(v - m);
        float s = e;
#pragma unroll
        for (int off = 8; off; off >>= 1)
            s += __shfl_xor_sync(0xffffffffu, s, off);
        if (gn < N_NODES) out[gn * OUTC + c_out] = v - m - logf(s);
    }
}

// ---------------- launch: kernel launches ONLY ----------------
extern "C" void kernel_launch(void* const* d_in, const int* in_sizes, int n_in,
                              void* d_out, int out_size) {
    const float* x   = (const float*)d_in[0];
    const int*   ei  = (const int*)d_in[1];   // int32 (JAX x64 disabled)
    const float* W1l = (const float*)d_in[2];
    const float* b1  = (const float*)d_in[3];
    const float* W1r = (const float*)d_in[4];
    const float* g1  = (const float*)d_in[5];
    const float* be1 = (const float*)d_in[6];
    const float* W2l = (const float*)d_in[7];
    const float* b2  = (const float*)d_in[8];
    const float* W2r = (const float*)d_in[9];
    const float* g2  = (const float*)d_in[10];
    const float* be2 = (const float*)d_in[11];
    const float* W3l = (const float*)d_in[12];
    const float* b3  = (const float*)d_in[13];
    const float* W3r = (const float*)d_in[14];
    float* out = (float*)d_out;

    // --- CSR build ---
    zero_deg_kernel<<<NG, 256>>>();
    hist_kernel<<<E4G, 256>>>(ei);
    chunk_sum_kernel<<<NG, 256>>>();
    scan_chunks_kernel<<<1, 256>>>();
    scan_within_kernel<<<NG, 256>>>();
    scatter_kernel<<<E4G, 256>>>(ei);

    // --- layer 1 (raw x) ---
    seg_min_kernel<<<SM4G, 256>>>(x, 0);
    linear64_kernel<<<LTG, 256>>>(x, 0, W1l, W1r, b1);
    bn_stats_kernel<<<1, 256>>>(g1, be1);

    // --- layer 2 (h1 = relu(bn1(bufB)) applied on load) ---
    seg_min_kernel<<<SM4G, 256>>>(x, 1);
    linear64_kernel<<<LTG, 256>>>(x, 1, W2l, W2r, b2);
    bn_stats_kernel<<<1, 256>>>(g2, be2);

    // --- layer 3 (h2 = relu(bn2(bufB)) on load; log_softmax into d_out) ---
    seg_min_kernel<<<SM4G, 256>>>(x, 1);
    linear16_ls_kernel<<<LTG, 256>>>(W3l, W3r, b3, out);
}

// round 11
// speedup vs baseline: 1.0007x; 1.0007x over previous
#include <cuda_runtime.h>
#include <math.h>

#define N_NODES 50000
#define N_EDGES 800000
#define C 64
#define OUTC 16
#define NG 196          // ceil(N_NODES/256)
#define E4G 782         // ceil(N_EDGES/4/256)
#define LTG 782         // ceil(N_NODES/64)
#define SM4G 3125       // N_NODES/16 (exact)
#define BN_EPS 1e-5f
typedef unsigned long long ull;

// ---- packed f32x2 helpers (sm_103a FFMA2) ----
#define FMA2(d, a, b, c) \
    asm("fma.rn.f32x2 %0, %1, %2, %3;" : "=l"(d) : "l"(a), "l"(b), "l"(c))
#define PACKF2(out, lo, hi) \
    asm("mov.b64 %0, {%1, %2};" : "=l"(out) : "r"(__float_as_uint(lo)), "r"(__float_as_uint(hi)))
#define UNPACKF2(lo, hi, in) \
    { unsigned int _l, _h; asm("mov.b64 {%0, %1}, %2;" : "=r"(_l), "=r"(_h) : "l"(in)); \
      lo = __uint_as_float(_l); hi = __uint_as_float(_h); }

// ---------------- device scratch ----------------
__device__ float g_bufA[N_NODES * C];     // agg (segment-min output)
__device__ float g_bufB[N_NODES * C];     // pre-BN linear output
__device__ float g_partS[LTG * C];
__device__ float g_partQ[LTG * C];
__device__ float g_bnp[2 * C];            // [scale | shift]
__device__ int   g_deg[N_NODES];
__device__ int   g_rowptr[N_NODES + 1];
__device__ int   g_cursor[N_NODES];
__device__ int   g_col[N_EDGES];
__device__ int   g_chunksum[256];
__device__ int   g_chunkoff[256];

// ---------------- CSR build ----------------
__global__ void zero_deg_kernel() {
    int i = blockIdx.x * 256 + threadIdx.x;
    if (i < N_NODES) g_deg[i] = 0;
}

// edge_index is int32 (JAX x64 disabled); 4 edges per thread via int4.
__global__ void hist_kernel(const int* __restrict__ ei) {
    int e4 = blockIdx.x * 256 + threadIdx.x;
    if (e4 < N_EDGES / 4) {
        int4 d = ((const int4*)(ei + N_EDGES))[e4];
        atomicAdd(&g_deg[d.x], 1);
        atomicAdd(&g_deg[d.y], 1);
        atomicAdd(&g_deg[d.z], 1);
        atomicAdd(&g_deg[d.w], 1);
    }
}

__global__ void chunk_sum_kernel() {
    __shared__ int sh[256];
    int b = blockIdx.x, t = threadIdx.x;
    int i = b * 256 + t;
    sh[t] = (i < N_NODES) ? g_deg[i] : 0;
    __syncthreads();
    for (int off = 128; off; off >>= 1) {
        if (t < off) sh[t] += sh[t + off];
        __syncthreads();
    }
    if (t == 0) g_chunksum[b] = sh[0];
}

__global__ void scan_chunks_kernel() {
    __shared__ int sh[256];
    int t = threadIdx.x;
    int v = (t < NG) ? g_chunksum[t] : 0;
    sh[t] = v;
    __syncthreads();
    for (int off = 1; off < 256; off <<= 1) {
        int add = (t >= off) ? sh[t - off] : 0;
        __syncthreads();
        sh[t] += add;
        __syncthreads();
    }
    if (t < NG) g_chunkoff[t] = sh[t] - v;
    if (t == 255) g_rowptr[N_NODES] = sh[255];
}

__global__ void scan_within_kernel() {
    __shared__ int sh[256];
    int b = blockIdx.x, t = threadIdx.x;
    int i = b * 256 + t;
    int v = (i < N_NODES) ? g_deg[i] : 0;
    sh[t] = v;
    __syncthreads();
    for (int off = 1; off < 256; off <<= 1) {
        int add = (t >= off) ? sh[t - off] : 0;
        __syncthreads();
        sh[t] += add;
        __syncthreads();
    }
    if (i < N_NODES) {
        int r = g_chunkoff[b] + sh[t] - v;
        g_rowptr[i] = r;
        g_cursor[i] = r;
    }
}

__global__ void scatter_kernel(const int* __restrict__ ei) {
    int e4 = blockIdx.x * 256 + threadIdx.x;
    if (e4 < N_EDGES / 4) {
        int4 s = ((const int4*)ei)[e4];
        int4 d = ((const int4*)(ei + N_EDGES))[e4];
        g_col[atomicAdd(&g_cursor[d.x], 1)] = s.x;
        g_col[atomicAdd(&g_cursor[d.y], 1)] = s.y;
        g_col[atomicAdd(&g_cursor[d.z], 1)] = s.z;
        g_col[atomicAdd(&g_cursor[d.w], 1)] = s.w;
    }
}

// ---------------- segment-min gather (float4, fused BN+ReLU on load) --------
// 16 lanes per node (4 channels each via float4); 16 nodes per 256-thread block.
// mode 0: gather raw xin rows. mode 1: gather relu(bn(g_bufB)) rows.
__global__ void seg_min_kernel(const float* __restrict__ xin, int mode) {
    int tid = threadIdx.x;
    int node = blockIdx.x * 16 + (tid >> 4);
    int c4 = tid & 15;
    const float4* src = (const float4*)(mode ? (const float*)g_bufB : xin);
    float4 sc, sh;
    if (mode) {
        sc = *(const float4*)&g_bnp[c4 * 4];
        sh = *(const float4*)&g_bnp[64 + c4 * 4];
    }
    int beg = g_rowptr[node];
    int end = g_rowptr[node + 1];
    const float INF = __int_as_float(0x7f800000);
    float4 m0 = {INF, INF, INF, INF}, m1 = m0, m2 = m0, m3 = m0;
    int e = beg;
    for (; e + 4 <= end; e += 4) {
        int s0 = g_col[e], s1 = g_col[e + 1], s2 = g_col[e + 2], s3 = g_col[e + 3];
        float4 v0 = src[s0 * 16 + c4];
        float4 v1 = src[s1 * 16 + c4];
        float4 v2 = src[s2 * 16 + c4];
        float4 v3 = src[s3 * 16 + c4];
        if (mode) {
            v0.x = fmaxf(v0.x * sc.x + sh.x, 0.f); v0.y = fmaxf(v0.y * sc.y + sh.y, 0.f);
            v0.z = fmaxf(v0.z * sc.z + sh.z, 0.f); v0.w = fmaxf(v0.w * sc.w + sh.w, 0.f);
            v1.x = fmaxf(v1.x * sc.x + sh.x, 0.f); v1.y = fmaxf(v1.y * sc.y + sh.y, 0.f);
            v1.z = fmaxf(v1.z * sc.z + sh.z, 0.f); v1.w = fmaxf(v1.w * sc.w + sh.w, 0.f);
            v2.x = fmaxf(v2.x * sc.x + sh.x, 0.f); v2.y = fmaxf(v2.y * sc.y + sh.y, 0.f);
            v2.z = fmaxf(v2.z * sc.z + sh.z, 0.f); v2.w = fmaxf(v2.w * sc.w + sh.w, 0.f);
            v3.x = fmaxf(v3.x * sc.x + sh.x, 0.f); v3.y = fmaxf(v3.y * sc.y + sh.y, 0.f);
            v3.z = fmaxf(v3.z * sc.z + sh.z, 0.f); v3.w = fmaxf(v3.w * sc.w + sh.w, 0.f);
        }
        m0.x = fminf(m0.x, v0.x); m0.y = fminf(m0.y, v0.y); m0.z = fminf(m0.z, v0.z); m0.w = fminf(m0.w, v0.w);
        m1.x = fminf(m1.x, v1.x); m1.y = fminf(m1.y, v1.y); m1.z = fminf(m1.z, v1.z); m1.w = fminf(m1.w, v1.w);
        m2.x = fminf(m2.x, v2.x); m2.y = fminf(m2.y, v2.y); m2.z = fminf(m2.z, v2.z); m2.w = fminf(m2.w, v2.w);
        m3.x = fminf(m3.x, v3.x); m3.y = fminf(m3.y, v3.y); m3.z = fminf(m3.z, v3.z); m3.w = fminf(m3.w, v3.w);
    }
    for (; e < end; e++) {
        float4 v = src[g_col[e] * 16 + c4];
        if (mode) {
            v.x = fmaxf(v.x * sc.x + sh.x, 0.f); v.y = fmaxf(v.y * sc.y + sh.y, 0.f);
            v.z = fmaxf(v.z * sc.z + sh.z, 0.f); v.w = fmaxf(v.w * sc.w + sh.w, 0.f);
        }
        m0.x = fminf(m0.x, v.x); m0.y = fminf(m0.y, v.y);
        m0.z = fminf(m0.z, v.z); m0.w = fminf(m0.w, v.w);
    }
    float4 m;
    m.x = fminf(fminf(m0.x, m1.x), fminf(m2.x, m3.x));
    m.y = fminf(fminf(m0.y, m1.y), fminf(m2.y, m3.y));
    m.z = fminf(fminf(m0.z, m1.z), fminf(m2.z, m3.z));
    m.w = fminf(fminf(m0.w, m1.w), fminf(m2.w, m3.w));
    if (beg >= end) m = make_float4(0.f, 0.f, 0.f, 0.f);
    ((float4*)g_bufA)[node * 16 + c4] = m;
}

// ---------------- fused dual-GEMM 64->64 via FFMA2 + BN partials -------------
// 256 threads, 64-node tile. Thread (cg=tid&15, slot=tid>>4) owns channel
// pairs {2cg,2cg+1} and {2cg+32,2cg+33} x nodes {slot, slot+16, slot+32, slot+48}.
#define MMA64() \
    _Pragma("unroll 4") \
    for (int ci = 0; ci < 64; ci++) { \
        ull bw0 = *(const ull*)&sW[ci * 64 + 2 * cg]; \
        ull bw1 = *(const ull*)&sW[ci * 64 + 2 * cg + 32]; \
        float x0 = sX[slot * 65 + ci]; \
        float x1 = sX[(slot + 16) * 65 + ci]; \
        float x2 = sX[(slot + 32) * 65 + ci]; \
        float x3 = sX[(slot + 48) * 65 + ci]; \
        ull a0, a1, a2, a3; \
        PACKF2(a0, x0, x0); PACKF2(a1, x1, x1); PACKF2(a2, x2, x2); PACKF2(a3, x3, x3); \
        FMA2(acc[0][0], a0, bw0, acc[0][0]); FMA2(acc[1][0], a0, bw1, acc[1][0]); \
        FMA2(acc[0][1], a1, bw0, acc[0][1]); FMA2(acc[1][1], a1, bw1, acc[1][1]); \
        FMA2(acc[0][2], a2, bw0, acc[0][2]); FMA2(acc[1][2], a2, bw1, acc[1][2]); \
        FMA2(acc[0][3], a3, bw0, acc[0][3]); FMA2(acc[1][3], a3, bw1, acc[1][3]); \
    }

__global__ void linear64_kernel(const float* __restrict__ xin, int use_bn,
                                const float* __restrict__ Wl,
                                const float* __restrict__ Wr,
                                const float* __restrict__ bias) {
    __shared__ __align__(16) float sW[64 * 64];
    __shared__ __align__(16) float sX[64 * 65];
    __shared__ float sRS[64 * 16];
    __shared__ float sRQ[64 * 16];

    const float* h2 = use_bn ? (const float*)g_bufB : xin;
    int tid = threadIdx.x;
    int base = blockIdx.x * 64;
    int cg = tid & 15, slot = tid >> 4;

    ull acc[2][4];
    {
        float2 bp0 = *(const float2*)&bias[2 * cg];
        float2 bp1 = *(const float2*)&bias[2 * cg + 32];
        ull b0, b1;
        PACKF2(b0, bp0.x, bp0.y);
        PACKF2(b1, bp1.x, bp1.y);
#pragma unroll
        for (int j = 0; j < 4; j++) { acc[0][j] = b0; acc[1][j] = b1; }
    }

    // ---- pass 1: Wl x agg ----
    for (int q = tid; q < 4096; q += 256) sW[q] = Wl[q];
    for (int q = tid; q < 4096; q += 256) {
        int nd = q >> 6, c = q & 63, gn = base + nd;
        sX[nd * 65 + c] = (gn < N_NODES) ? g_bufA[gn * C + c] : 0.0f;
    }
    __syncthreads();
    MMA64();
    __syncthreads();

    // ---- pass 2: Wr x h (BN+ReLU fused on load for layer >= 2) ----
    for (int q = tid; q < 4096; q += 256) sW[q] = Wr[q];
    for (int q = tid; q < 4096; q += 256) {
        int nd = q >> 6, c = q & 63, gn = base + nd;
        float v = (gn < N_NODES) ? h2[gn * C + c] : 0.0f;
        if (use_bn) v = fmaxf(v * g_bnp[c] + g_bnp[64 + c], 0.0f);
        sX[nd * 65 + c] = v;
    }
    __syncthreads();
    MMA64();

    // ---- epilogue: write output pairs + deterministic BN partials ----
#pragma unroll
    for (int p = 0; p < 2; p++) {
        int co0 = 2 * cg + 32 * p;
        float s1l = 0.f, s2l = 0.f, s1h = 0.f, s2h = 0.f;
#pragma unroll
        for (int j = 0; j < 4; j++) {
            int gn = base + slot + 16 * j;
            float lo, hi;
            UNPACKF2(lo, hi, acc[p][j]);
            if (gn < N_NODES) {
                *(float2*)&g_bufB[gn * C + co0] = make_float2(lo, hi);
                s1l += lo; s2l += lo * lo;
                s1h += hi; s2h += hi * hi;
            }
        }
        sRS[co0 * 16 + slot] = s1l;
        sRQ[co0 * 16 + slot] = s2l;
        sRS[(co0 + 1) * 16 + slot] = s1h;
        sRQ[(co0 + 1) * 16 + slot] = s2h;
    }
    __syncthreads();
    if (tid < 64) {
        float t1 = 0.0f, t2 = 0.0f;
#pragma unroll
        for (int s = 0; s < 16; s++) {
            t1 += sRS[tid * 16 + s];
            t2 += sRQ[tid * 16 + s];
        }
        g_partS[blockIdx.x * 64 + tid] = t1;
        g_partQ[blockIdx.x * 64 + tid] = t2;
    }
}

// ---------------- BN stats: deterministic reduce + scale/shift prep ---------
__global__ void bn_stats_kernel(const float* __restrict__ g, const float* __restrict__ be) {
    __shared__ float redS[256], redQ[256];
    int t = threadIdx.x;         // 256
    int c = t & 63, part = t >> 6;
    float s = 0.0f, q = 0.0f;
    for (int i = part; i < LTG; i += 4) {
        s += g_partS[i * 64 + c];
        q += g_partQ[i * 64 + c];
    }
    redS[t] = s;
    redQ[t] = q;
    __syncthreads();
    if (t < 64) {
        float S = redS[t] + redS[t + 64] + redS[t + 128] + redS[t + 192];
        float Q = redQ[t] + redQ[t + 64] + redQ[t + 128] + redQ[t + 192];
        float inv = 1.0f / (float)N_NODES;
        float mu = S * inv;
        float var = Q * inv - mu * mu;
        float sc = g[t] * rsqrtf(var + BN_EPS);
        g_bnp[t] = sc;
        g_bnp[64 + t] = be[t] - mu * sc;
    }
}

// ---------------- fused dual-GEMM 64->16 + log_softmax ----------------------
__global__ void linear16_ls_kernel(const float* __restrict__ Wl,
                                   const float* __restrict__ Wr,
                                   const float* __restrict__ b,
                                   float* __restrict__ out) {
    __shared__ float sWl[64 * 16], sWr[64 * 16];
    __shared__ float sA[64 * 65], sH[64 * 65];

    int tid = threadIdx.x;
    int base = blockIdx.x * 64;

    for (int q = tid; q < 1024; q += 256) { sWl[q] = Wl[q]; sWr[q] = Wr[q]; }
    for (int q = tid; q < 4096; q += 256) {
        int nd = q >> 6, c = q & 63, gn = base + nd;
        float a = 0.0f, hh = 0.0f;
        if (gn < N_NODES) {
            a = g_bufA[gn * C + c];
            hh = fmaxf(g_bufB[gn * C + c] * g_bnp[c] + g_bnp[64 + c], 0.0f);
        }
        sA[nd * 65 + c] = a;
        sH[nd * 65 + c] = hh;
    }
    __syncthreads();

    int c_out = tid & 15, nslot = tid >> 4;
    float acc[4];
    float bb = b[c_out];
#pragma unroll
    for (int j = 0; j < 4; j++) acc[j] = bb;

#pragma unroll 8
    for (int ci = 0; ci < 64; ci++) {
        float wl = sWl[ci * 16 + c_out];
        float wr = sWr[ci * 16 + c_out];
#pragma unroll
        for (int j = 0; j < 4; j++) {
            int nd = nslot + 16 * j;
            acc[j] += sA[nd * 65 + ci] * wl + sH[nd * 65 + ci] * wr;
        }
    }

#pragma unroll
    for (int j = 0; j < 4; j++) {
        int gn = base + nslot + 16 * j;
        float v = acc[j];
        float m = v;
#pragma unroll
        for (int off = 8; off; off >>= 1)
            m = fmaxf(m, __shfl_xor_sync(0xffffffffu, m, off));
        float e = expf(v - m);
        float s = e;
#pragma unroll
        for (int off = 8; off; off >>= 1)
            s += __shfl_xor_sync(0xffffffffu, s, off);
        if (gn < N_NODES) out[gn * OUTC + c_out] = v - m - logf(s);
    }
}

// ---------------- launch: kernel launches ONLY ----------------
extern "C" void kernel_launch(void* const* d_in, const int* in_sizes, int n_in,
                              void* d_out, int out_size) {
    const float* x   = (const float*)d_in[0];
    const int*   ei  = (const int*)d_in[1];   // int32 (JAX x64 disabled)
    const float* W1l = (const float*)d_in[2];
    const float* b1  = (const float*)d_in[3];
    const float* W1r = (const float*)d_in[4];
    const float* g1  = (const float*)d_in[5];
    const float* be1 = (const float*)d_in[6];
    const float* W2l = (const float*)d_in[7];
    const float* b2  = (const float*)d_in[8];
    const float* W2r = (const float*)d_in[9];
    const float* g2  = (const float*)d_in[10];
    const float* be2 = (const float*)d_in[11];
    const float* W3l = (const float*)d_in[12];
    const float* b3  = (const float*)d_in[13];
    const float* W3r = (const float*)d_in[14];
    float* out = (float*)d_out;

    // --- CSR build ---
    zero_deg_kernel<<<NG, 256>>>();
    hist_kernel<<<E4G, 256>>>(ei);
    chunk_sum_kernel<<<NG, 256>>>();
    scan_chunks_kernel<<<1, 256>>>();
    scan_within_kernel<<<NG, 256>>>();
    scatter_kernel<<<E4G, 256>>>(ei);

    // --- layer 1 (raw x) ---
    seg_min_kernel<<<SM4G, 256>>>(x, 0);
    linear64_kernel<<<LTG, 256>>>(x, 0, W1l, W1r, b1);
    bn_stats_kernel<<<1, 256>>>(g1, be1);

    // --- layer 2 (h1 = relu(bn1(bufB)) applied on load) ---
    seg_min_kernel<<<SM4G, 256>>>(x, 1);
    linear64_kernel<<<LTG, 256>>>(x, 1, W2l, W2r, b2);
    bn_stats_kernel<<<1, 256>>>(g2, be2);

    // --- layer 3 (h2 = relu(bn2(bufB)) on load; log_softmax into d_out) ---
    seg_min_kernel<<<SM4G, 256>>>(x, 1);
    linear16_ls_kernel<<<LTG, 256>>>(W3l, W3r, b3, out);
}

// round 13
// speedup vs baseline: 1.0656x; 1.0649x over previous
#include <cuda_runtime.h>
#include <math.h>

#define N_NODES 50000
#define N_EDGES 800000
#define C 64
#define OUTC 16
#define NG 196          // ceil(N_NODES/256)
#define E4G 782         // ceil(N_EDGES/4/256)
#define LTG 782         // ceil(N_NODES/64)
#define BN_EPS 1e-5f
typedef unsigned long long ull;

// ---- packed f32x2 helpers (sm_103a FFMA2) ----
#define FMA2(d, a, b, c) \
    asm("fma.rn.f32x2 %0, %1, %2, %3;" : "=l"(d) : "l"(a), "l"(b), "l"(c))
#define PACKF2(out, lo, hi) \
    asm("mov.b64 %0, {%1, %2};" : "=l"(out) : "r"(__float_as_uint(lo)), "r"(__float_as_uint(hi)))
#define UNPACKF2(lo, hi, in) \
    { unsigned int _l, _h; asm("mov.b64 {%0, %1}, %2;" : "=r"(_l), "=r"(_h) : "l"(in)); \
      lo = __uint_as_float(_l); hi = __uint_as_float(_h); }

// ---------------- device scratch ----------------
__device__ __align__(16) float g_bufB[N_NODES * C];   // layer-1 pre-BN output
__device__ __align__(16) float g_bufD[N_NODES * C];   // layer-2 pre-BN output
__device__ float g_partS[LTG * C];
__device__ float g_partQ[LTG * C];
__device__ __align__(16) float g_bnp[2 * C];          // [scale | shift]
__device__ int   g_deg[N_NODES];
__device__ int   g_start[N_NODES];
__device__ int   g_end[N_NODES];
__device__ int   g_cursor[N_NODES];
__device__ int   g_col[N_EDGES];
__device__ int   g_total;
__device__ int   g_done;

// ---------------- CSR build (3 kernels) ----------------
// edge_index is int32 (JAX x64 disabled); 4 edges per thread via int4.
// g_deg arrives zeroed (zero-init on load; offsets_kernel re-zeroes each replay).
__global__ void hist_kernel(const int* __restrict__ ei) {
    if (blockIdx.x == 0 && threadIdx.x == 0) { g_total = 0; g_done = 0; }
    int e4 = blockIdx.x * 256 + threadIdx.x;
    if (e4 < N_EDGES / 4) {
        int4 d = ((const int4*)(ei + N_EDGES))[e4];
        atomicAdd(&g_deg[d.x], 1);
        atomicAdd(&g_deg[d.y], 1);
        atomicAdd(&g_deg[d.z], 1);
        atomicAdd(&g_deg[d.w], 1);
    }
}

// Range allocation: block-level scan + one atomicAdd per block on g_total.
// Placement order is atomic-arrival-dependent but the OUTPUT is invariant
// (min over a segment does not depend on where the segment lives).
__global__ void offsets_kernel() {
    __shared__ int wtot[8];
    __shared__ int blockbase;
    int t = threadIdx.x, i = blockIdx.x * 256 + t;
    int lane = t & 31, w = t >> 5;
    int d = (i < N_NODES) ? g_deg[i] : 0;
    int sc = d;
#pragma unroll
    for (int off = 1; off < 32; off <<= 1) {
        int n = __shfl_up_sync(0xffffffffu, sc, off);
        if (lane >= off) sc += n;
    }
    if (lane == 31) wtot[w] = sc;
    __syncthreads();
    if (w == 0) {
        int v = (lane < 8) ? wtot[lane] : 0;
#pragma unroll
        for (int off = 1; off < 8; off <<= 1) {
            int n = __shfl_up_sync(0xffffffffu, v, off);
            if (lane >= off) v += n;
        }
        if (lane < 8) wtot[lane] = v;
        if (lane == 7) blockbase = atomicAdd(&g_total, v);
    }
    __syncthreads();
    int beg = blockbase + ((w == 0) ? 0 : wtot[w - 1]) + sc - d;
    if (i < N_NODES) {
        g_start[i]  = beg;
        g_end[i]    = beg + d;
        g_cursor[i] = beg;
        g_deg[i]    = 0;     // ready for next graph replay
    }
}

__global__ void scatter_kernel(const int* __restrict__ ei) {
    int e4 = blockIdx.x * 256 + threadIdx.x;
    if (e4 < N_EDGES / 4) {
        int4 s = ((const int4*)ei)[e4];
        int4 d = ((const int4*)(ei + N_EDGES))[e4];
        g_col[atomicAdd(&g_cursor[d.x], 1)] = s.x;
        g_col[atomicAdd(&g_cursor[d.y], 1)] = s.y;
        g_col[atomicAdd(&g_cursor[d.z], 1)] = s.z;
        g_col[atomicAdd(&g_cursor[d.w], 1)] = s.w;
    }
}

// ---------------- raw segment-min for one node / one channel quad ----------
__device__ __forceinline__ float4 gmin4(const float4* __restrict__ src,
                                        int beg, int end, int c4) {
    const float INF = __int_as_float(0x7f800000);
    float4 m0 = {INF, INF, INF, INF}, m1 = m0, m2 = m0, m3 = m0;
    int e = beg;
    for (; e + 4 <= end; e += 4) {
        int s0 = g_col[e], s1 = g_col[e + 1], s2 = g_col[e + 2], s3 = g_col[e + 3];
        float4 v0 = src[s0 * 16 + c4];
        float4 v1 = src[s1 * 16 + c4];
        float4 v2 = src[s2 * 16 + c4];
        float4 v3 = src[s3 * 16 + c4];
        m0.x = fminf(m0.x, v0.x); m0.y = fminf(m0.y, v0.y); m0.z = fminf(m0.z, v0.z); m0.w = fminf(m0.w, v0.w);
        m1.x = fminf(m1.x, v1.x); m1.y = fminf(m1.y, v1.y); m1.z = fminf(m1.z, v1.z); m1.w = fminf(m1.w, v1.w);
        m2.x = fminf(m2.x, v2.x); m2.y = fminf(m2.y, v2.y); m2.z = fminf(m2.z, v2.z); m2.w = fminf(m2.w, v2.w);
        m3.x = fminf(m3.x, v3.x); m3.y = fminf(m3.y, v3.y); m3.z = fminf(m3.z, v3.z); m3.w = fminf(m3.w, v3.w);
    }
    for (; e < end; e++) {
        float4 v = src[g_col[e] * 16 + c4];
        m0.x = fminf(m0.x, v.x); m0.y = fminf(m0.y, v.y);
        m0.z = fminf(m0.z, v.z); m0.w = fminf(m0.w, v.w);
    }
    float4 m;
    m.x = fminf(fminf(m0.x, m1.x), fminf(m2.x, m3.x));
    m.y = fminf(fminf(m0.y, m1.y), fminf(m2.y, m3.y));
    m.z = fminf(fminf(m0.z, m1.z), fminf(m2.z, m3.z));
    m.w = fminf(fminf(m0.w, m1.w), fminf(m2.w, m3.w));
    return m;
}

// ---------------- fused layer: gather-min + dual-GEMM 64->64 + BN stats -----
// 256 threads, 64-node tile. GEMM thread (cg=tid&15, slot=tid>>4) owns channel
// pairs {2cg,2cg+1},{2cg+32,2cg+33} x nodes {slot,+16,+32,+48} via FFMA2.
// Gather thread (c4=tid&15, sub=tid>>4): 4 sweeps of 16 nodes, float4 channels.
// BN+ReLU applied once post-min (valid: scale=gamma*rsqrt(var)>0, monotone).
// DOUBLE-BUFFERED: layer1 xin->g_bufB; layer2 g_bufB->g_bufD (no in-place race).
#define MMA64() \
    _Pragma("unroll 4") \
    for (int ci = 0; ci < 64; ci++) { \
        ull bw0 = *(const ull*)&sW[ci * 64 + 2 * cg]; \
        ull bw1 = *(const ull*)&sW[ci * 64 + 2 * cg + 32]; \
        float x0 = sX[slot * 65 + ci]; \
        float x1 = sX[(slot + 16) * 65 + ci]; \
        float x2 = sX[(slot + 32) * 65 + ci]; \
        float x3 = sX[(slot + 48) * 65 + ci]; \
        ull a0, a1, a2, a3; \
        PACKF2(a0, x0, x0); PACKF2(a1, x1, x1); PACKF2(a2, x2, x2); PACKF2(a3, x3, x3); \
        FMA2(acc[0][0], a0, bw0, acc[0][0]); FMA2(acc[1][0], a0, bw1, acc[1][0]); \
        FMA2(acc[0][1], a1, bw0, acc[0][1]); FMA2(acc[1][1], a1, bw1, acc[1][1]); \
        FMA2(acc[0][2], a2, bw0, acc[0][2]); FMA2(acc[1][2], a2, bw1, acc[1][2]); \
        FMA2(acc[0][3], a3, bw0, acc[0][3]); FMA2(acc[1][3], a3, bw1, acc[1][3]); \
    }

__global__ void layer64_kernel(const float* __restrict__ xin, int use_bn,
                               const float* __restrict__ Wl,
                               const float* __restrict__ Wr,
                               const float* __restrict__ bias,
                               const float* __restrict__ gam,
                               const float* __restrict__ bet) {
    __shared__ __align__(16) float sW[64 * 64];
    __shared__ __align__(16) float sX[64 * 65];
    __shared__ float sRS[64 * 16];
    __shared__ float sRQ[64 * 16];
    __shared__ bool amLast;

    int tid = threadIdx.x;
    int base = blockIdx.x * 64;
    const float* hsrc = use_bn ? (const float*)g_bufB : xin;
    float* dst = use_bn ? g_bufD : g_bufB;      // double buffer: never in-place
    const float4* src4 = (const float4*)hsrc;

    // Wl -> smem (independent of gather; issue early)
    for (int q = tid; q < 4096; q += 256) sW[q] = Wl[q];

    // ---- gather-min phase: fill sX with agg rows ----
    int c4 = tid & 15, sub = tid >> 4;
    float4 sc, sh;
    if (use_bn) {
        sc = *(const float4*)&g_bnp[c4 * 4];
        sh = *(const float4*)&g_bnp[64 + c4 * 4];
    }
#pragma unroll
    for (int s = 0; s < 4; s++) {
        int nd = s * 16 + sub, node = base + nd;
        float4 m = make_float4(0.f, 0.f, 0.f, 0.f);
        if (node < N_NODES) {
            int beg = g_start[node], end = g_end[node];
            if (beg < end) {
                m = gmin4(src4, beg, end, c4);
                if (use_bn) {
                    m.x = fmaxf(m.x * sc.x + sh.x, 0.f);
                    m.y = fmaxf(m.y * sc.y + sh.y, 0.f);
                    m.z = fmaxf(m.z * sc.z + sh.z, 0.f);
                    m.w = fmaxf(m.w * sc.w + sh.w, 0.f);
                }
            }
        }
        int o = nd * 65 + 4 * c4;
        sX[o] = m.x; sX[o + 1] = m.y; sX[o + 2] = m.z; sX[o + 3] = m.w;
    }
    __syncthreads();

    // ---- GEMM pass 1: Wl x agg ----
    int cg = c4, slot = sub;
    ull acc[2][4];
    {
        float2 bp0 = *(const float2*)&bias[2 * cg];
        float2 bp1 = *(const float2*)&bias[2 * cg + 32];
        ull b0, b1;
        PACKF2(b0, bp0.x, bp0.y);
        PACKF2(b1, bp1.x, bp1.y);
#pragma unroll
        for (int j = 0; j < 4; j++) { acc[0][j] = b0; acc[1][j] = b1; }
    }
    MMA64();
    __syncthreads();

    // ---- GEMM pass 2: Wr x h (BN+ReLU fused on load for layer >= 2) ----
    for (int q = tid; q < 4096; q += 256) sW[q] = Wr[q];
    for (int q = tid; q < 4096; q += 256) {
        int nd = q >> 6, c = q & 63, gn = base + nd;
        float v = (gn < N_NODES) ? hsrc[gn * C + c] : 0.0f;
        if (use_bn) v = fmaxf(v * g_bnp[c] + g_bnp[64 + c], 0.0f);
        sX[nd * 65 + c] = v;
    }
    __syncthreads();
    MMA64();

    // ---- epilogue: store output pairs + BN partials ----
#pragma unroll
    for (int p = 0; p < 2; p++) {
        int co0 = 2 * cg + 32 * p;
        float s1l = 0.f, s2l = 0.f, s1h = 0.f, s2h = 0.f;
#pragma unroll
        for (int j = 0; j < 4; j++) {
            int gn = base + slot + 16 * j;
            float lo, hi;
            UNPACKF2(lo, hi, acc[p][j]);
            if (gn < N_NODES) {
                *(float2*)&dst[gn * C + co0] = make_float2(lo, hi);
                s1l += lo; s2l += lo * lo;
                s1h += hi; s2h += hi * hi;
            }
        }
        sRS[co0 * 16 + slot] = s1l;
        sRQ[co0 * 16 + slot] = s2l;
        sRS[(co0 + 1) * 16 + slot] = s1h;
        sRQ[(co0 + 1) * 16 + slot] = s2h;
    }
    __syncthreads();
    if (tid < 64) {
        float t1 = 0.0f, t2 = 0.0f;
#pragma unroll
        for (int s = 0; s < 16; s++) {
            t1 += sRS[tid * 16 + s];
            t2 += sRQ[tid * 16 + s];
        }
        g_partS[blockIdx.x * 64 + tid] = t1;
        g_partQ[blockIdx.x * 64 + tid] = t2;
    }
    __threadfence();
    __syncthreads();

    // ---- last block computes BN scale/shift (fixed-order, deterministic) ----
    if (tid == 0) amLast = (atomicAdd(&g_done, 1) == LTG - 1);
    __syncthreads();
    if (amLast) {
        __threadfence();
        int c = tid & 63, part = tid >> 6;
        float s = 0.0f, q = 0.0f;
        for (int i = part; i < LTG; i += 4) {
            s += g_partS[i * 64 + c];
            q += g_partQ[i * 64 + c];
        }
        sRS[tid] = s;
        sRQ[tid] = q;
        __syncthreads();
        if (tid < 64) {
            float S = sRS[tid] + sRS[tid + 64] + sRS[tid + 128] + sRS[tid + 192];
            float Q = sRQ[tid] + sRQ[tid + 64] + sRQ[tid + 128] + sRQ[tid + 192];
            float inv = 1.0f / (float)N_NODES;
            float mu = S * inv;
            float var = Q * inv - mu * mu;
            float scale = gam[tid] * rsqrtf(var + BN_EPS);
            g_bnp[tid] = scale;
            g_bnp[64 + tid] = bet[tid] - mu * scale;
        }
        if (tid == 0) g_done = 0;   // ready for next layer / replay
    }
}

// ---------------- fused layer 3: gather-min + dual-GEMM 64->16 + log_softmax
__global__ void layer16_kernel(const float* __restrict__ Wl,
                               const float* __restrict__ Wr,
                               const float* __restrict__ b,
                               float* __restrict__ out) {
    __shared__ float sWl[64 * 16], sWr[64 * 16];
    __shared__ __align__(16) float sA[64 * 65];
    __shared__ float sH[64 * 65];

    int tid = threadIdx.x;
    int base = blockIdx.x * 64;
    const float4* src4 = (const float4*)g_bufD;   // layer-2 output buffer

    for (int q = tid; q < 1024; q += 256) { sWl[q] = Wl[q]; sWr[q] = Wr[q]; }

    // gather-min of h2 rows (bn2+relu applied post-min, monotone) into sA
    int c4 = tid & 15, sub = tid >> 4;
    float4 sc = *(const float4*)&g_bnp[c4 * 4];
    float4 sh = *(const float4*)&g_bnp[64 + c4 * 4];
#pragma unroll
    for (int s = 0; s < 4; s++) {
        int nd = s * 16 + sub, node = base + nd;
        float4 m = make_float4(0.f, 0.f, 0.f, 0.f);
        if (node < N_NODES) {
            int beg = g_start[node], end = g_end[node];
            if (beg < end) {
                m = gmin4(src4, beg, end, c4);
                m.x = fmaxf(m.x * sc.x + sh.x, 0.f);
                m.y = fmaxf(m.y * sc.y + sh.y, 0.f);
                m.z = fmaxf(m.z * sc.z + sh.z, 0.f);
                m.w = fmaxf(m.w * sc.w + sh.w, 0.f);
            }
        }
        int o = nd * 65 + 4 * c4;
        sA[o] = m.x; sA[o + 1] = m.y; sA[o + 2] = m.z; sA[o + 3] = m.w;
    }
    // h2 rows (contiguous) with bn2+relu into sH
    for (int q = tid; q < 4096; q += 256) {
        int nd = q >> 6, c = q & 63, gn = base + nd;
        float v = (gn < N_NODES)
                      ? fmaxf(g_bufD[gn * C + c] * g_bnp[c] + g_bnp[64 + c], 0.0f)
                      : 0.0f;
        sH[nd * 65 + c] = v;
    }
    __syncthreads();

    int c_out = tid & 15, nslot = tid >> 4;
    float acc[4];
    float bb = b[c_out];
#pragma unroll
    for (int j = 0; j < 4; j++) acc[j] = bb;

#pragma unroll 8
    for (int ci = 0; ci < 64; ci++) {
        float wl = sWl[ci * 16 + c_out];
        float wr = sWr[ci * 16 + c_out];
#pragma unroll
        for (int j = 0; j < 4; j++) {
            int nd = nslot + 16 * j;
            acc[j] += sA[nd * 65 + ci] * wl + sH[nd * 65 + ci] * wr;
        }
    }

    // log_softmax: 16 channels of a node live in 16 consecutive lanes.
#pragma unroll
    for (int j = 0; j < 4; j++) {
        int gn = base + nslot + 16 * j;
        float v = acc[j];
        float m = v;
#pragma unroll
        for (int off = 8; off; off >>= 1)
            m = fmaxf(m, __shfl_xor_sync(0xffffffffu, m, off));
        float e = expf(v - m);
        float s = e;
#pragma unroll
        for (int off = 8; off; off >>= 1)
            s += __shfl_xor_sync(0xffffffffu, s, off);
        if (gn < N_NODES) out[gn * OUTC + c_out] = v - m - logf(s);
    }
}

// ---------------- launch: 6 kernel launches ----------------
extern "C" void kernel_launch(void* const* d_in, const int* in_sizes, int n_in,
                              void* d_out, int out_size) {
    const float* x   = (const float*)d_in[0];
    const int*   ei  = (const int*)d_in[1];   // int32 (JAX x64 disabled)
    const float* W1l = (const float*)d_in[2];
    const float* b1  = (const float*)d_in[3];
    const float* W1r = (const float*)d_in[4];
    const float* g1  = (const float*)d_in[5];
    const float* be1 = (const float*)d_in[6];
    const float* W2l = (const float*)d_in[7];
    const float* b2  = (const float*)d_in[8];
    const float* W2r = (const float*)d_in[9];
    const float* g2  = (const float*)d_in[10];
    const float* be2 = (const float*)d_in[11];
    const float* W3l = (const float*)d_in[12];
    const float* b3  = (const float*)d_in[13];
    const float* W3r = (const float*)d_in[14];
    float* out = (float*)d_out;

    hist_kernel<<<E4G, 256>>>(ei);
    offsets_kernel<<<NG, 256>>>();
    scatter_kernel<<<E4G, 256>>>(ei);

    layer64_kernel<<<LTG, 256>>>(x, 0, W1l, W1r, b1, g1, be1);
    layer64_kernel<<<LTG, 256>>>(x, 1, W2l, W2r, b2, g2, be2);
    layer16_kernel<<<LTG, 256>>>(W3l, W3r, b3, out);
}

// round 14
// speedup vs baseline: 1.0657x; 1.0001x over previous
#include <cuda_runtime.h>
#include <math.h>

#define N_NODES 50000
#define N_EDGES 800000
#define C 64
#define OUTC 16
#define NG 196          // ceil(N_NODES/256)
#define E4G 782         // ceil(N_EDGES/4/256)
#define LTG 782         // ceil(N_NODES/64)
#define BN_EPS 1e-5f
typedef unsigned long long ull;

// ---- packed f32x2 helpers (sm_103a FFMA2) ----
#define FMA2(d, a, b, c) \
    asm("fma.rn.f32x2 %0, %1, %2, %3;" : "=l"(d) : "l"(a), "l"(b), "l"(c))
#define PACKF2(out, lo, hi) \
    asm("mov.b64 %0, {%1, %2};" : "=l"(out) : "r"(__float_as_uint(lo)), "r"(__float_as_uint(hi)))
#define UNPACKF2(lo, hi, in) \
    { unsigned int _l, _h; asm("mov.b64 {%0, %1}, %2;" : "=r"(_l), "=r"(_h) : "l"(in)); \
      lo = __uint_as_float(_l); hi = __uint_as_float(_h); }

// ---------------- device scratch ----------------
__device__ __align__(16) float g_bufB[N_NODES * C];   // layer-1 pre-BN output
__device__ __align__(16) float g_bufD[N_NODES * C];   // layer-2 pre-BN output
__device__ float g_partS[LTG * C];
__device__ float g_partQ[LTG * C];
__device__ __align__(16) float g_bnp[2 * C];          // [scale | shift]
__device__ int   g_deg[N_NODES];
__device__ int   g_start[N_NODES];
__device__ int   g_end[N_NODES];
__device__ int   g_cursor[N_NODES];
__device__ int   g_col[N_EDGES];
__device__ int   g_total;
__device__ int   g_done;

// ---------------- CSR build (3 kernels) ----------------
// edge_index is int32 (JAX x64 disabled); 4 edges per thread via int4.
// g_deg arrives zeroed (zero-init on load; offsets_kernel re-zeroes each replay).
__global__ void hist_kernel(const int* __restrict__ ei) {
    if (blockIdx.x == 0 && threadIdx.x == 0) { g_total = 0; g_done = 0; }
    int e4 = blockIdx.x * 256 + threadIdx.x;
    if (e4 < N_EDGES / 4) {
        int4 d = ((const int4*)(ei + N_EDGES))[e4];
        atomicAdd(&g_deg[d.x], 1);
        atomicAdd(&g_deg[d.y], 1);
        atomicAdd(&g_deg[d.z], 1);
        atomicAdd(&g_deg[d.w], 1);
    }
}

// Range allocation: block-level scan + one atomicAdd per block on g_total.
// Placement order is atomic-arrival-dependent but the OUTPUT is invariant
// (min over a segment does not depend on where the segment lives).
__global__ void offsets_kernel() {
    __shared__ int wtot[8];
    __shared__ int blockbase;
    int t = threadIdx.x, i = blockIdx.x * 256 + t;
    int lane = t & 31, w = t >> 5;
    int d = (i < N_NODES) ? g_deg[i] : 0;
    int sc = d;
#pragma unroll
    for (int off = 1; off < 32; off <<= 1) {
        int n = __shfl_up_sync(0xffffffffu, sc, off);
        if (lane >= off) sc += n;
    }
    if (lane == 31) wtot[w] = sc;
    __syncthreads();
    if (w == 0) {
        int v = (lane < 8) ? wtot[lane] : 0;
#pragma unroll
        for (int off = 1; off < 8; off <<= 1) {
            int n = __shfl_up_sync(0xffffffffu, v, off);
            if (lane >= off) v += n;
        }
        if (lane < 8) wtot[lane] = v;
        if (lane == 7) blockbase = atomicAdd(&g_total, v);
    }
    __syncthreads();
    int beg = blockbase + ((w == 0) ? 0 : wtot[w - 1]) + sc - d;
    if (i < N_NODES) {
        g_start[i]  = beg;
        g_end[i]    = beg + d;
        g_cursor[i] = beg;
        g_deg[i]    = 0;     // ready for next graph replay
    }
}

__global__ void scatter_kernel(const int* __restrict__ ei) {
    int e4 = blockIdx.x * 256 + threadIdx.x;
    if (e4 < N_EDGES / 4) {
        int4 s = ((const int4*)ei)[e4];
        int4 d = ((const int4*)(ei + N_EDGES))[e4];
        g_col[atomicAdd(&g_cursor[d.x], 1)] = s.x;
        g_col[atomicAdd(&g_cursor[d.y], 1)] = s.y;
        g_col[atomicAdd(&g_cursor[d.z], 1)] = s.z;
        g_col[atomicAdd(&g_cursor[d.w], 1)] = s.w;
    }
}

// ---------------- raw segment-min for one node / one channel quad ----------
__device__ __forceinline__ float4 gmin4(const float4* __restrict__ src,
                                        int beg, int end, int c4) {
    const float INF = __int_as_float(0x7f800000);
    float4 m0 = {INF, INF, INF, INF}, m1 = m0, m2 = m0, m3 = m0;
    int e = beg;
    for (; e + 4 <= end; e += 4) {
        int s0 = g_col[e], s1 = g_col[e + 1], s2 = g_col[e + 2], s3 = g_col[e + 3];
        float4 v0 = src[s0 * 16 + c4];
        float4 v1 = src[s1 * 16 + c4];
        float4 v2 = src[s2 * 16 + c4];
        float4 v3 = src[s3 * 16 + c4];
        m0.x = fminf(m0.x, v0.x); m0.y = fminf(m0.y, v0.y); m0.z = fminf(m0.z, v0.z); m0.w = fminf(m0.w, v0.w);
        m1.x = fminf(m1.x, v1.x); m1.y = fminf(m1.y, v1.y); m1.z = fminf(m1.z, v1.z); m1.w = fminf(m1.w, v1.w);
        m2.x = fminf(m2.x, v2.x); m2.y = fminf(m2.y, v2.y); m2.z = fminf(m2.z, v2.z); m2.w = fminf(m2.w, v2.w);
        m3.x = fminf(m3.x, v3.x); m3.y = fminf(m3.y, v3.y); m3.z = fminf(m3.z, v3.z); m3.w = fminf(m3.w, v3.w);
    }
    for (; e < end; e++) {
        float4 v = src[g_col[e] * 16 + c4];
        m0.x = fminf(m0.x, v.x); m0.y = fminf(m0.y, v.y);
        m0.z = fminf(m0.z, v.z); m0.w = fminf(m0.w, v.w);
    }
    float4 m;
    m.x = fminf(fminf(m0.x, m1.x), fminf(m2.x, m3.x));
    m.y = fminf(fminf(m0.y, m1.y), fminf(m2.y, m3.y));
    m.z = fminf(fminf(m0.z, m1.z), fminf(m2.z, m3.z));
    m.w = fminf(fminf(m0.w, m1.w), fminf(m2.w, m3.w));
    return m;
}

// ---------------- fused layer: gather-min + dual-GEMM 64->64 + BN stats -----
// 256 threads, 64-node tile. GEMM thread (cg=tid&15, slot=tid>>4) owns channel
// pairs {2cg,2cg+1},{2cg+32,2cg+33} x nodes {slot,+16,+32,+48} via FFMA2.
// Gather thread (c4=tid&15, sub=tid>>4): 4 sweeps of 16 nodes, float4 channels.
// BN+ReLU applied once post-min (valid: scale=gamma*rsqrt(var)>0, monotone).
// DOUBLE-BUFFERED: layer1 xin->g_bufB; layer2 g_bufB->g_bufD (no in-place race).
#define MMA64() \
    _Pragma("unroll 4") \
    for (int ci = 0; ci < 64; ci++) { \
        ull bw0 = *(const ull*)&sW[ci * 64 + 2 * cg]; \
        ull bw1 = *(const ull*)&sW[ci * 64 + 2 * cg + 32]; \
        float x0 = sX[slot * 65 + ci]; \
        float x1 = sX[(slot + 16) * 65 + ci]; \
        float x2 = sX[(slot + 32) * 65 + ci]; \
        float x3 = sX[(slot + 48) * 65 + ci]; \
        ull a0, a1, a2, a3; \
        PACKF2(a0, x0, x0); PACKF2(a1, x1, x1); PACKF2(a2, x2, x2); PACKF2(a3, x3, x3); \
        FMA2(acc[0][0], a0, bw0, acc[0][0]); FMA2(acc[1][0], a0, bw1, acc[1][0]); \
        FMA2(acc[0][1], a1, bw0, acc[0][1]); FMA2(acc[1][1], a1, bw1, acc[1][1]); \
        FMA2(acc[0][2], a2, bw0, acc[0][2]); FMA2(acc[1][2], a2, bw1, acc[1][2]); \
        FMA2(acc[0][3], a3, bw0, acc[0][3]); FMA2(acc[1][3], a3, bw1, acc[1][3]); \
    }

__global__ void layer64_kernel(const float* __restrict__ xin, int use_bn,
                               const float* __restrict__ Wl,
                               const float* __restrict__ Wr,
                               const float* __restrict__ bias,
                               const float* __restrict__ gam,
                               const float* __restrict__ bet) {
    __shared__ __align__(16) float sW[64 * 64];
    __shared__ __align__(16) float sX[64 * 65];
    __shared__ float sRS[64 * 16];
    __shared__ float sRQ[64 * 16];
    __shared__ bool amLast;

    int tid = threadIdx.x;
    int base = blockIdx.x * 64;
    const float* hsrc = use_bn ? (const float*)g_bufB : xin;
    float* dst = use_bn ? g_bufD : g_bufB;      // double buffer: never in-place
    const float4* src4 = (const float4*)hsrc;

    // Wl -> smem (independent of gather; issue early)
    for (int q = tid; q < 4096; q += 256) sW[q] = Wl[q];

    // ---- gather-min phase: fill sX with agg rows ----
    int c4 = tid & 15, sub = tid >> 4;
    float4 sc, sh;
    if (use_bn) {
        sc = *(const float4*)&g_bnp[c4 * 4];
        sh = *(const float4*)&g_bnp[64 + c4 * 4];
    }
#pragma unroll
    for (int s = 0; s < 4; s++) {
        int nd = s * 16 + sub, node = base + nd;
        float4 m = make_float4(0.f, 0.f, 0.f, 0.f);
        if (node < N_NODES) {
            int beg = g_start[node], end = g_end[node];
            if (beg < end) {
                m = gmin4(src4, beg, end, c4);
                if (use_bn) {
                    m.x = fmaxf(m.x * sc.x + sh.x, 0.f);
                    m.y = fmaxf(m.y * sc.y + sh.y, 0.f);
                    m.z = fmaxf(m.z * sc.z + sh.z, 0.f);
                    m.w = fmaxf(m.w * sc.w + sh.w, 0.f);
                }
            }
        }
        int o = nd * 65 + 4 * c4;
        sX[o] = m.x; sX[o + 1] = m.y; sX[o + 2] = m.z; sX[o + 3] = m.w;
    }
    __syncthreads();

    // ---- GEMM pass 1: Wl x agg ----
    int cg = c4, slot = sub;
    ull acc[2][4];
    {
        float2 bp0 = *(const float2*)&bias[2 * cg];
        float2 bp1 = *(const float2*)&bias[2 * cg + 32];
        ull b0, b1;
        PACKF2(b0, bp0.x, bp0.y);
        PACKF2(b1, bp1.x, bp1.y);
#pragma unroll
        for (int j = 0; j < 4; j++) { acc[0][j] = b0; acc[1][j] = b1; }
    }
    MMA64();
    __syncthreads();

    // ---- GEMM pass 2: Wr x h (BN+ReLU fused on load for layer >= 2) ----
    for (int q = tid; q < 4096; q += 256) sW[q] = Wr[q];
    for (int q = tid; q < 4096; q += 256) {
        int nd = q >> 6, c = q & 63, gn = base + nd;
        float v = (gn < N_NODES) ? hsrc[gn * C + c] : 0.0f;
        if (use_bn) v = fmaxf(v * g_bnp[c] + g_bnp[64 + c], 0.0f);
        sX[nd * 65 + c] = v;
    }
    __syncthreads();
    MMA64();

    // ---- epilogue: store output pairs + BN partials ----
#pragma unroll
    for (int p = 0; p < 2; p++) {
        int co0 = 2 * cg + 32 * p;
        float s1l = 0.f, s2l = 0.f, s1h = 0.f, s2h = 0.f;
#pragma unroll
        for (int j = 0; j < 4; j++) {
            int gn = base + slot + 16 * j;
            float lo, hi;
            UNPACKF2(lo, hi, acc[p][j]);
            if (gn < N_NODES) {
                *(float2*)&dst[gn * C + co0] = make_float2(lo, hi);
                s1l += lo; s2l += lo * lo;
                s1h += hi; s2h += hi * hi;
            }
        }
        sRS[co0 * 16 + slot] = s1l;
        sRQ[co0 * 16 + slot] = s2l;
        sRS[(co0 + 1) * 16 + slot] = s1h;
        sRQ[(co0 + 1) * 16 + slot] = s2h;
    }
    __syncthreads();
    if (tid < 64) {
        float t1 = 0.0f, t2 = 0.0f;
#pragma unroll
        for (int s = 0; s < 16; s++) {
            t1 += sRS[tid * 16 + s];
            t2 += sRQ[tid * 16 + s];
        }
        g_partS[blockIdx.x * 64 + tid] = t1;
        g_partQ[blockIdx.x * 64 + tid] = t2;
    }
    __threadfence();
    __syncthreads();

    // ---- last block computes BN scale/shift (fixed-order, deterministic) ----
    if (tid == 0) amLast = (atomicAdd(&g_done, 1) == LTG - 1);
    __syncthreads();
    if (amLast) {
        __threadfence();
        int c = tid & 63, part = tid >> 6;
        float s = 0.0f, q = 0.0f;
        for (int i = part; i < LTG; i += 4) {
            s += g_partS[i * 64 + c];
            q += g_partQ[i * 64 + c];
        }
        sRS[tid] = s;
        sRQ[tid] = q;
        __syncthreads();
        if (tid < 64) {
            float S = sRS[tid] + sRS[tid + 64] + sRS[tid + 128] + sRS[tid + 192];
            float Q = sRQ[tid] + sRQ[tid + 64] + sRQ[tid + 128] + sRQ[tid + 192];
            float inv = 1.0f / (float)N_NODES;
            float mu = S * inv;
            float var = Q * inv - mu * mu;
            float scale = gam[tid] * rsqrtf(var + BN_EPS);
            g_bnp[tid] = scale;
            g_bnp[64 + tid] = bet[tid] - mu * scale;
        }
        if (tid == 0) g_done = 0;   // ready for next layer / replay
    }
}

// ---------------- fused layer 3: gather-min + dual-GEMM 64->16 + log_softmax
__global__ void layer16_kernel(const float* __restrict__ Wl,
                               const float* __restrict__ Wr,
                               const float* __restrict__ b,
                               float* __restrict__ out) {
    __shared__ float sWl[64 * 16], sWr[64 * 16];
    __shared__ __align__(16) float sA[64 * 65];
    __shared__ float sH[64 * 65];

    int tid = threadIdx.x;
    int base = blockIdx.x * 64;
    const float4* src4 = (const float4*)g_bufD;   // layer-2 output buffer

    for (int q = tid; q < 1024; q += 256) { sWl[q] = Wl[q]; sWr[q] = Wr[q]; }

    // gather-min of h2 rows (bn2+relu applied post-min, monotone) into sA
    int c4 = tid & 15, sub = tid >> 4;
    float4 sc = *(const float4*)&g_bnp[c4 * 4];
    float4 sh = *(const float4*)&g_bnp[64 + c4 * 4];
#pragma unroll
    for (int s = 0; s < 4; s++) {
        int nd = s * 16 + sub, node = base + nd;
        float4 m = make_float4(0.f, 0.f, 0.f, 0.f);
        if (node < N_NODES) {
            int beg = g_start[node], end = g_end[node];
            if (beg < end) {
                m = gmin4(src4, beg, end, c4);
                m.x = fmaxf(m.x * sc.x + sh.x, 0.f);
                m.y = fmaxf(m.y * sc.y + sh.y, 0.f);
                m.z = fmaxf(m.z * sc.z + sh.z, 0.f);
                m.w = fmaxf(m.w * sc.w + sh.w, 0.f);
            }
        }
        int o = nd * 65 + 4 * c4;
        sA[o] = m.x; sA[o + 1] = m.y; sA[o + 2] = m.z; sA[o + 3] = m.w;
    }
    // h2 rows (contiguous) with bn2+relu into sH
    for (int q = tid; q < 4096; q += 256) {
        int nd = q >> 6, c = q & 63, gn = base + nd;
        float v = (gn < N_NODES)
                      ? fmaxf(g_bufD[gn * C + c] * g_bnp[c] + g_bnp[64 + c], 0.0f)
                      : 0.0f;
        sH[nd * 65 + c] = v;
    }
    __syncthreads();

    int c_out = tid & 15, nslot = tid >> 4;
    float acc[4];
    float bb = b[c_out];
#pragma unroll
    for (int j = 0; j < 4; j++) acc[j] = bb;

#pragma unroll 8
    for (int ci = 0; ci < 64; ci++) {
        float wl = sWl[ci * 16 + c_out];
        float wr = sWr[ci * 16 + c_out];
#pragma unroll
        for (int j = 0; j < 4; j++) {
            int nd = nslot + 16 * j;
            acc[j] += sA[nd * 65 + ci] * wl + sH[nd * 65 + ci] * wr;
        }
    }

    // log_softmax: 16 channels of a node live in 16 consecutive lanes.
#pragma unroll
    for (int j = 0; j < 4; j++) {
        int gn = base + nslot + 16 * j;
        float v = acc[j];
        float m = v;
#pragma unroll
        for (int off = 8; off; off >>= 1)
            m = fmaxf(m, __shfl_xor_sync(0xffffffffu, m, off));
        float e = expf(v - m);
        float s = e;
#pragma unroll
        for (int off = 8; off; off >>= 1)
            s += __shfl_xor_sync(0xffffffffu, s, off);
        if (gn < N_NODES) out[gn * OUTC + c_out] = v - m - logf(s);
    }
}

// ---------------- launch: 6 kernel launches ----------------
extern "C" void kernel_launch(void* const* d_in, const int* in_sizes, int n_in,
                              void* d_out, int out_size) {
    const float* x   = (const float*)d_in[0];
    const int*   ei  = (const int*)d_in[1];   // int32 (JAX x64 disabled)
    const float* W1l = (const float*)d_in[2];
    const float* b1  = (const float*)d_in[3];
    const float* W1r = (const float*)d_in[4];
    const float* g1  = (const float*)d_in[5];
    const float* be1 = (const float*)d_in[6];
    const float* W2l = (const float*)d_in[7];
    const float* b2  = (const float*)d_in[8];
    const float* W2r = (const float*)d_in[9];
    const float* g2  = (const float*)d_in[10];
    const float* be2 = (const float*)d_in[11];
    const float* W3l = (const float*)d_in[12];
    const float* b3  = (const float*)d_in[13];
    const float* W3r = (const float*)d_in[14];
    float* out = (float*)d_out;

    hist_kernel<<<E4G, 256>>>(ei);
    offsets_kernel<<<NG, 256>>>();
    scatter_kernel<<<E4G, 256>>>(ei);

    layer64_kernel<<<LTG, 256>>>(x, 0, W1l, W1r, b1, g1, be1);
    layer64_kernel<<<LTG, 256>>>(x, 1, W2l, W2r, b2, g2, be2);
    layer16_kernel<<<LTG, 256>>>(W3l, W3r, b3, out);
}

// round 15
// speedup vs baseline: 1.0887x; 1.0216x over previous
#include <cuda_runtime.h>
#include <math.h>

#define N_NODES 50000
#define N_EDGES 800000
#define C 64
#define OUTC 16
#define NG 196          // ceil(N_NODES/256)
#define E4G 782         // ceil(N_EDGES/4/256)
#define LTG 782         // ceil(N_NODES/64)
#define BN_EPS 1e-5f
typedef unsigned long long ull;

// ---- packed f32x2 helpers (sm_103a FFMA2) ----
#define FMA2(d, a, b, c) \
    asm("fma.rn.f32x2 %0, %1, %2, %3;" : "=l"(d) : "l"(a), "l"(b), "l"(c))
#define PACKF2(out, lo, hi) \
    asm("mov.b64 %0, {%1, %2};" : "=l"(out) : "r"(__float_as_uint(lo)), "r"(__float_as_uint(hi)))
#define UNPACKF2(lo, hi, in) \
    { unsigned int _l, _h; asm("mov.b64 {%0, %1}, %2;" : "=r"(_l), "=r"(_h) : "l"(in)); \
      lo = __uint_as_float(_l); hi = __uint_as_float(_h); }

// ---------------- device scratch ----------------
__device__ __align__(16) float g_bufB[N_NODES * C];   // layer-1 pre-BN output
__device__ __align__(16) float g_bufD[N_NODES * C];   // layer-2 pre-BN output
__device__ float g_partS[LTG * C];
__device__ float g_partQ[LTG * C];
__device__ __align__(16) float g_bnp[2 * C];          // [scale | shift]
__device__ int   g_deg[N_NODES];
__device__ int   g_start[N_NODES];
__device__ int   g_end[N_NODES];
__device__ int   g_cursor[N_NODES];
__device__ int   g_col[N_EDGES];
__device__ int   g_total;
__device__ int   g_done;

// ---------------- CSR build (3 kernels) ----------------
__global__ void hist_kernel(const int* __restrict__ ei) {
    if (blockIdx.x == 0 && threadIdx.x == 0) { g_total = 0; g_done = 0; }
    int e4 = blockIdx.x * 256 + threadIdx.x;
    if (e4 < N_EDGES / 4) {
        int4 d = ((const int4*)(ei + N_EDGES))[e4];
        atomicAdd(&g_deg[d.x], 1);
        atomicAdd(&g_deg[d.y], 1);
        atomicAdd(&g_deg[d.z], 1);
        atomicAdd(&g_deg[d.w], 1);
    }
}

// Unordered range allocation (min is placement-invariant).
__global__ void offsets_kernel() {
    __shared__ int wtot[8];
    __shared__ int blockbase;
    int t = threadIdx.x, i = blockIdx.x * 256 + t;
    int lane = t & 31, w = t >> 5;
    int d = (i < N_NODES) ? g_deg[i] : 0;
    int sc = d;
#pragma unroll
    for (int off = 1; off < 32; off <<= 1) {
        int n = __shfl_up_sync(0xffffffffu, sc, off);
        if (lane >= off) sc += n;
    }
    if (lane == 31) wtot[w] = sc;
    __syncthreads();
    if (w == 0) {
        int v = (lane < 8) ? wtot[lane] : 0;
#pragma unroll
        for (int off = 1; off < 8; off <<= 1) {
            int n = __shfl_up_sync(0xffffffffu, v, off);
            if (lane >= off) v += n;
        }
        if (lane < 8) wtot[lane] = v;
        if (lane == 7) blockbase = atomicAdd(&g_total, v);
    }
    __syncthreads();
    int beg = blockbase + ((w == 0) ? 0 : wtot[w - 1]) + sc - d;
    if (i < N_NODES) {
        g_start[i]  = beg;
        g_end[i]    = beg + d;
        g_cursor[i] = beg;
        g_deg[i]    = 0;     // ready for next graph replay
    }
}

__global__ void scatter_kernel(const int* __restrict__ ei) {
    int e4 = blockIdx.x * 256 + threadIdx.x;
    if (e4 < N_EDGES / 4) {
        int4 s = ((const int4*)ei)[e4];
        int4 d = ((const int4*)(ei + N_EDGES))[e4];
        g_col[atomicAdd(&g_cursor[d.x], 1)] = s.x;
        g_col[atomicAdd(&g_cursor[d.y], 1)] = s.y;
        g_col[atomicAdd(&g_cursor[d.z], 1)] = s.z;
        g_col[atomicAdd(&g_cursor[d.w], 1)] = s.w;
    }
}

#define FMIN4(a, v) \
    { (a).x = fminf((a).x, (v).x); (a).y = fminf((a).y, (v).y); \
      (a).z = fminf((a).z, (v).z); (a).w = fminf((a).w, (v).w); }

// ---------------- interleaved 4-node gather-min into sX --------------------
// Thread (c4 = tid&15 channel quad, sub = tid>>4) handles nodes base+sub+16s.
// All 4 node streams advance together: 8 independent loads in flight per
// iteration, fully independent addressing across iterations (high MLP).
// Clamped index + predicated min handles ragged degrees.
__device__ __forceinline__ void gather4(const float4* __restrict__ src4,
                                        int base, int c4, int sub,
                                        float* __restrict__ sX, bool bn) {
    int begs[4], degs[4], last[4];
#pragma unroll
    for (int s = 0; s < 4; s++) {
        int node = base + s * 16 + sub;
        int b = 0, d = 0;
        if (node < N_NODES) { b = g_start[node]; d = g_end[node] - b; }
        begs[s] = b; degs[s] = d;
        last[s] = (d > 0) ? (b + d - 1) : 0;
    }
    int maxd = max(max(degs[0], degs[1]), max(degs[2], degs[3]));
    const float INF = __int_as_float(0x7f800000);
    float4 a0 = {INF, INF, INF, INF}, a1 = a0, a2 = a0, a3 = a0;
    for (int k = 0; k < maxd; k++) {
        int c0 = g_col[min(begs[0] + k, last[0])];
        int c1 = g_col[min(begs[1] + k, last[1])];
        int c2 = g_col[min(begs[2] + k, last[2])];
        int c3 = g_col[min(begs[3] + k, last[3])];
        float4 v0 = src4[c0 * 16 + c4];
        float4 v1 = src4[c1 * 16 + c4];
        float4 v2 = src4[c2 * 16 + c4];
        float4 v3 = src4[c3 * 16 + c4];
        if (k < degs[0]) FMIN4(a0, v0);
        if (k < degs[1]) FMIN4(a1, v1);
        if (k < degs[2]) FMIN4(a2, v2);
        if (k < degs[3]) FMIN4(a3, v3);
    }
    float4 sc, sh;
    if (bn) {
        sc = *(const float4*)&g_bnp[c4 * 4];
        sh = *(const float4*)&g_bnp[64 + c4 * 4];
    }
    float4 accs[4] = {a0, a1, a2, a3};
#pragma unroll
    for (int s = 0; s < 4; s++) {
        float4 m = accs[s];
        if (degs[s] == 0) m = make_float4(0.f, 0.f, 0.f, 0.f);
        else if (bn) {
            m.x = fmaxf(m.x * sc.x + sh.x, 0.f);
            m.y = fmaxf(m.y * sc.y + sh.y, 0.f);
            m.z = fmaxf(m.z * sc.z + sh.z, 0.f);
            m.w = fmaxf(m.w * sc.w + sh.w, 0.f);
        }
        int o = (s * 16 + sub) * 65 + 4 * c4;
        sX[o] = m.x; sX[o + 1] = m.y; sX[o + 2] = m.z; sX[o + 3] = m.w;
    }
}

// ---------------- fused layer: gather-min + dual-GEMM 64->64 + BN stats -----
#define MMA64() \
    _Pragma("unroll 4") \
    for (int ci = 0; ci < 64; ci++) { \
        ull bw0 = *(const ull*)&sW[ci * 64 + 2 * cg]; \
        ull bw1 = *(const ull*)&sW[ci * 64 + 2 * cg + 32]; \
        float x0 = sX[slot * 65 + ci]; \
        float x1 = sX[(slot + 16) * 65 + ci]; \
        float x2 = sX[(slot + 32) * 65 + ci]; \
        float x3 = sX[(slot + 48) * 65 + ci]; \
        ull a0, a1, a2, a3; \
        PACKF2(a0, x0, x0); PACKF2(a1, x1, x1); PACKF2(a2, x2, x2); PACKF2(a3, x3, x3); \
        FMA2(acc[0][0], a0, bw0, acc[0][0]); FMA2(acc[1][0], a0, bw1, acc[1][0]); \
        FMA2(acc[0][1], a1, bw0, acc[0][1]); FMA2(acc[1][1], a1, bw1, acc[1][1]); \
        FMA2(acc[0][2], a2, bw0, acc[0][2]); FMA2(acc[1][2], a2, bw1, acc[1][2]); \
        FMA2(acc[0][3], a3, bw0, acc[0][3]); FMA2(acc[1][3], a3, bw1, acc[1][3]); \
    }

__global__ void __launch_bounds__(256, 5)
layer64_kernel(const float* __restrict__ xin, int use_bn,
               const float* __restrict__ Wl,
               const float* __restrict__ Wr,
               const float* __restrict__ bias,
               const float* __restrict__ gam,
               const float* __restrict__ bet) {
    __shared__ __align__(16) float sW[64 * 64];
    __shared__ __align__(16) float sX[64 * 65];
    __shared__ bool amLast;
    float* sRS = sX;              // aliased: sX dead after last MMA
    float* sRQ = sX + 1024;

    int tid = threadIdx.x;
    int base = blockIdx.x * 64;
    const float* hsrc = use_bn ? (const float*)g_bufB : xin;
    float* dst = use_bn ? g_bufD : g_bufB;      // double buffer: never in-place
    const float4* src4 = (const float4*)hsrc;

    // Wl -> smem (float4)
    for (int q = tid; q < 1024; q += 256)
        ((float4*)sW)[q] = ((const float4*)Wl)[q];

    // ---- gather-min phase ----
    int c4 = tid & 15, sub = tid >> 4;
    gather4(src4, base, c4, sub, sX, use_bn != 0);
    __syncthreads();

    // ---- GEMM pass 1: Wl x agg ----
    int cg = c4, slot = sub;
    ull acc[2][4];
    {
        float2 bp0 = *(const float2*)&bias[2 * cg];
        float2 bp1 = *(const float2*)&bias[2 * cg + 32];
        ull b0, b1;
        PACKF2(b0, bp0.x, bp0.y);
        PACKF2(b1, bp1.x, bp1.y);
#pragma unroll
        for (int j = 0; j < 4; j++) { acc[0][j] = b0; acc[1][j] = b1; }
    }
    MMA64();
    __syncthreads();

    // ---- GEMM pass 2: Wr x h (BN+ReLU fused on load; float4) ----
    for (int q = tid; q < 1024; q += 256)
        ((float4*)sW)[q] = ((const float4*)Wr)[q];
    for (int q = tid; q < 1024; q += 256) {
        int nd = q >> 4, cq = q & 15, gn = base + nd;
        float4 v = make_float4(0.f, 0.f, 0.f, 0.f);
        if (gn < N_NODES) {
            v = src4[gn * 16 + cq];
            if (use_bn) {
                float4 bsc = *(const float4*)&g_bnp[cq * 4];
                float4 bsh = *(const float4*)&g_bnp[64 + cq * 4];
                v.x = fmaxf(v.x * bsc.x + bsh.x, 0.f);
                v.y = fmaxf(v.y * bsc.y + bsh.y, 0.f);
                v.z = fmaxf(v.z * bsc.z + bsh.z, 0.f);
                v.w = fmaxf(v.w * bsc.w + bsh.w, 0.f);
            }
        }
        int o = nd * 65 + 4 * cq;
        sX[o] = v.x; sX[o + 1] = v.y; sX[o + 2] = v.z; sX[o + 3] = v.w;
    }
    __syncthreads();
    MMA64();
    __syncthreads();   // sX reads done; safe to alias sRS/sRQ

    // ---- epilogue: store output pairs + BN partials ----
#pragma unroll
    for (int p = 0; p < 2; p++) {
        int co0 = 2 * cg + 32 * p;
        float s1l = 0.f, s2l = 0.f, s1h = 0.f, s2h = 0.f;
#pragma unroll
        for (int j = 0; j < 4; j++) {
            int gn = base + slot + 16 * j;
            float lo, hi;
            UNPACKF2(lo, hi, acc[p][j]);
            if (gn < N_NODES) {
                *(float2*)&dst[gn * C + co0] = make_float2(lo, hi);
                s1l += lo; s2l += lo * lo;
                s1h += hi; s2h += hi * hi;
            }
        }
        sRS[co0 * 16 + slot] = s1l;
        sRQ[co0 * 16 + slot] = s2l;
        sRS[(co0 + 1) * 16 + slot] = s1h;
        sRQ[(co0 + 1) * 16 + slot] = s2h;
    }
    __syncthreads();
    if (tid < 64) {
        float t1 = 0.0f, t2 = 0.0f;
#pragma unroll
        for (int s = 0; s < 16; s++) {
            t1 += sRS[tid * 16 + s];
            t2 += sRQ[tid * 16 + s];
        }
        g_partS[blockIdx.x * 64 + tid] = t1;
        g_partQ[blockIdx.x * 64 + tid] = t2;
    }
    __threadfence();
    __syncthreads();

    // ---- last block computes BN scale/shift (fixed-order, deterministic) ----
    if (tid == 0) amLast = (atomicAdd(&g_done, 1) == LTG - 1);
    __syncthreads();
    if (amLast) {
        __threadfence();
        int c = tid & 63, part = tid >> 6;
        float s = 0.0f, q = 0.0f;
        for (int i = part; i < LTG; i += 4) {
            s += g_partS[i * 64 + c];
            q += g_partQ[i * 64 + c];
        }
        sRS[tid] = s;
        sRQ[tid] = q;
        __syncthreads();
        if (tid < 64) {
            float S = sRS[tid] + sRS[tid + 64] + sRS[tid + 128] + sRS[tid + 192];
            float Q = sRQ[tid] + sRQ[tid + 64] + sRQ[tid + 128] + sRQ[tid + 192];
            float inv = 1.0f / (float)N_NODES;
            float mu = S * inv;
            float var = Q * inv - mu * mu;
            float scale = gam[tid] * rsqrtf(var + BN_EPS);
            g_bnp[tid] = scale;
            g_bnp[64 + tid] = bet[tid] - mu * scale;
        }
        if (tid == 0) g_done = 0;   // ready for next layer / replay
    }
}

// ---------------- fused layer 3: gather-min + dual-GEMM 64->16 + log_softmax
__global__ void __launch_bounds__(256, 5)
layer16_kernel(const float* __restrict__ Wl,
               const float* __restrict__ Wr,
               const float* __restrict__ b,
               float* __restrict__ out) {
    __shared__ float sWl[64 * 16], sWr[64 * 16];
    __shared__ __align__(16) float sA[64 * 65];
    __shared__ __align__(16) float sH[64 * 65];

    int tid = threadIdx.x;
    int base = blockIdx.x * 64;
    const float4* src4 = (const float4*)g_bufD;   // layer-2 output buffer

    for (int q = tid; q < 1024; q += 256) { sWl[q] = Wl[q]; sWr[q] = Wr[q]; }

    // gather-min of h2 rows (bn2+relu post-min, monotone) into sA
    int c4 = tid & 15, sub = tid >> 4;
    gather4(src4, base, c4, sub, sA, true);

    // h2 rows (contiguous, float4) with bn2+relu into sH
    for (int q = tid; q < 1024; q += 256) {
        int nd = q >> 4, cq = q & 15, gn = base + nd;
        float4 v = make_float4(0.f, 0.f, 0.f, 0.f);
        if (gn < N_NODES) {
            v = src4[gn * 16 + cq];
            float4 bsc = *(const float4*)&g_bnp[cq * 4];
            float4 bsh = *(const float4*)&g_bnp[64 + cq * 4];
            v.x = fmaxf(v.x * bsc.x + bsh.x, 0.f);
            v.y = fmaxf(v.y * bsc.y + bsh.y, 0.f);
            v.z = fmaxf(v.z * bsc.z + bsh.z, 0.f);
            v.w = fmaxf(v.w * bsc.w + bsh.w, 0.f);
        }
        int o = nd * 65 + 4 * cq;
        sH[o] = v.x; sH[o + 1] = v.y; sH[o + 2] = v.z; sH[o + 3] = v.w;
    }
    __syncthreads();

    int c_out = tid & 15, nslot = tid >> 4;
    float acc[4];
    float bb = b[c_out];
#pragma unroll
    for (int j = 0; j < 4; j++) acc[j] = bb;

#pragma unroll 8
    for (int ci = 0; ci < 64; ci++) {
        float wl = sWl[ci * 16 + c_out];
        float wr = sWr[ci * 16 + c_out];
#pragma unroll
        for (int j = 0; j < 4; j++) {
            int nd = nslot + 16 * j;
            acc[j] += sA[nd * 65 + ci] * wl + sH[nd * 65 + ci] * wr;
        }
    }

    // log_softmax: 16 channels of a node live in 16 consecutive lanes.
#pragma unroll
    for (int j = 0; j < 4; j++) {
        int gn = base + nslot + 16 * j;
        float v = acc[j];
        float m = v;
#pragma unroll
        for (int off = 8; off; off >>= 1)
            m = fmaxf(m, __shfl_xor_sync(0xffffffffu, m, off));
        float e = expf(v - m);
        float s = e;
#pragma unroll
        for (int off = 8; off; off >>= 1)
            s += __shfl_xor_sync(0xffffffffu, s, off);
        if (gn < N_NODES) out[gn * OUTC + c_out] = v - m - logf(s);
    }
}

// ---------------- launch: 6 kernel launches ----------------
extern "C" void kernel_launch(void* const* d_in, const int* in_sizes, int n_in,
                              void* d_out, int out_size) {
    const float* x   = (const float*)d_in[0];
    const int*   ei  = (const int*)d_in[1];   // int32 (JAX x64 disabled)
    const float* W1l = (const float*)d_in[2];
    const float* b1  = (const float*)d_in[3];
    const float* W1r = (const float*)d_in[4];
    const float* g1  = (const float*)d_in[5];
    const float* be1 = (const float*)d_in[6];
    const float* W2l = (const float*)d_in[7];
    const float* b2  = (const float*)d_in[8];
    const float* W2r = (const float*)d_in[9];
    const float* g2  = (const float*)d_in[10];
    const float* be2 = (const float*)d_in[11];
    const float* W3l = (const float*)d_in[12];
    const float* b3  = (const float*)d_in[13];
    const float* W3r = (const float*)d_in[14];
    float* out = (float*)d_out;

    hist_kernel<<<E4G, 256>>>(ei);
    offsets_kernel<<<NG, 256>>>();
    scatter_kernel<<<E4G, 256>>>(ei);

    layer64_kernel<<<LTG, 256>>>(x, 0, W1l, W1r, b1, g1, be1);
    layer64_kernel<<<LTG, 256>>>(x, 1, W2l, W2r, b2, g2, be2);
    layer16_kernel<<<LTG, 256>>>(W3l, W3r, b3, out);
}

// round 16
// speedup vs baseline: 1.1538x; 1.0597x over previous
#include <cuda_runtime.h>
#include <math.h>

#define N_NODES 50000
#define N_EDGES 800000
#define C 64
#define OUTC 16
#define NG 196          // ceil(N_NODES/256)
#define E4G 782         // ceil(N_EDGES/4/256)
#define LTG 782         // ceil(N_NODES/64)
#define BN_EPS 1e-5f
typedef unsigned long long ull;

// ---- packed f32x2 helpers (sm_103a FFMA2) ----
#define FMA2(d, a, b, c) \
    asm("fma.rn.f32x2 %0, %1, %2, %3;" : "=l"(d) : "l"(a), "l"(b), "l"(c))
#define PACKF2(out, lo, hi) \
    asm("mov.b64 %0, {%1, %2};" : "=l"(out) : "r"(__float_as_uint(lo)), "r"(__float_as_uint(hi)))
#define UNPACKF2(lo, hi, in) \
    { unsigned int _l, _h; asm("mov.b64 {%0, %1}, %2;" : "=r"(_l), "=r"(_h) : "l"(in)); \
      lo = __uint_as_float(_l); hi = __uint_as_float(_h); }

// ---------------- device scratch ----------------
__device__ __align__(16) float g_bufB[N_NODES * C];   // layer-1 pre-BN output
__device__ __align__(16) float g_bufD[N_NODES * C];   // layer-2 pre-BN output
__device__ float g_partS[LTG * C];
__device__ float g_partQ[LTG * C];
__device__ __align__(16) float g_bnp[2 * C];          // [scale | shift]
__device__ int   g_deg[N_NODES];
__device__ int   g_start[N_NODES];
__device__ int   g_end[N_NODES];
__device__ int   g_cursor[N_NODES];
__device__ int   g_col[N_EDGES];
__device__ int   g_total;
__device__ int   g_done;

// ---------------- CSR build (3 kernels) ----------------
__global__ void hist_kernel(const int* __restrict__ ei) {
    if (blockIdx.x == 0 && threadIdx.x == 0) { g_total = 0; g_done = 0; }
    int e4 = blockIdx.x * 256 + threadIdx.x;
    if (e4 < N_EDGES / 4) {
        int4 d = ((const int4*)(ei + N_EDGES))[e4];
        atomicAdd(&g_deg[d.x], 1);
        atomicAdd(&g_deg[d.y], 1);
        atomicAdd(&g_deg[d.z], 1);
        atomicAdd(&g_deg[d.w], 1);
    }
}

// Unordered range allocation (min is placement-invariant).
__global__ void offsets_kernel() {
    __shared__ int wtot[8];
    __shared__ int blockbase;
    int t = threadIdx.x, i = blockIdx.x * 256 + t;
    int lane = t & 31, w = t >> 5;
    int d = (i < N_NODES) ? g_deg[i] : 0;
    int sc = d;
#pragma unroll
    for (int off = 1; off < 32; off <<= 1) {
        int n = __shfl_up_sync(0xffffffffu, sc, off);
        if (lane >= off) sc += n;
    }
    if (lane == 31) wtot[w] = sc;
    __syncthreads();
    if (w == 0) {
        int v = (lane < 8) ? wtot[lane] : 0;
#pragma unroll
        for (int off = 1; off < 8; off <<= 1) {
            int n = __shfl_up_sync(0xffffffffu, v, off);
            if (lane >= off) v += n;
        }
        if (lane < 8) wtot[lane] = v;
        if (lane == 7) blockbase = atomicAdd(&g_total, v);
    }
    __syncthreads();
    int beg = blockbase + ((w == 0) ? 0 : wtot[w - 1]) + sc - d;
    if (i < N_NODES) {
        g_start[i]  = beg;
        g_end[i]    = beg + d;
        g_cursor[i] = beg;
        g_deg[i]    = 0;     // ready for next graph replay
    }
}

__global__ void scatter_kernel(const int* __restrict__ ei) {
    int e4 = blockIdx.x * 256 + threadIdx.x;
    if (e4 < N_EDGES / 4) {
        int4 s = ((const int4*)ei)[e4];
        int4 d = ((const int4*)(ei + N_EDGES))[e4];
        g_col[atomicAdd(&g_cursor[d.x], 1)] = s.x;
        g_col[atomicAdd(&g_cursor[d.y], 1)] = s.y;
        g_col[atomicAdd(&g_cursor[d.z], 1)] = s.z;
        g_col[atomicAdd(&g_cursor[d.w], 1)] = s.w;
    }
}

#define FMIN4(a, v) \
    { (a).x = fminf((a).x, (v).x); (a).y = fminf((a).y, (v).y); \
      (a).z = fminf((a).z, (v).z); (a).w = fminf((a).w, (v).w); }

// ---------------- interleaved 4-node gather-min into sX --------------------
// Thread (c4 = tid&15 channel quad, sub = tid>>4) handles nodes base+sub+16s.
// 4 node streams advance together; col indices are software-pipelined one
// iteration ahead so feature loads never wait on a same-iteration col load.
// All loads + mins are PREDICATED on k<deg (no clamped duplicate traffic).
// Predicates are uniform across the 16 lanes of a sub-group (no divergence).
__device__ __forceinline__ void gather4(const float4* __restrict__ src4,
                                        int base, int c4, int sub,
                                        float* __restrict__ sX, bool bn) {
    int begs[4], degs[4];
#pragma unroll
    for (int s = 0; s < 4; s++) {
        int node = base + s * 16 + sub;
        int b = 0, d = 0;
        if (node < N_NODES) { b = g_start[node]; d = g_end[node] - b; }
        begs[s] = b; degs[s] = d;
    }
    int maxd = max(max(degs[0], degs[1]), max(degs[2], degs[3]));
    const float INF = __int_as_float(0x7f800000);
    float4 a0 = {INF, INF, INF, INF}, a1 = a0, a2 = a0, a3 = a0;

    int col[4];
#pragma unroll
    for (int s = 0; s < 4; s++)
        col[s] = (degs[s] > 0) ? g_col[begs[s]] : 0;

    for (int k = 0; k < maxd; k++) {
        // prefetch next iteration's col indices (predicated)
        int ncol[4];
#pragma unroll
        for (int s = 0; s < 4; s++)
            ncol[s] = (k + 1 < degs[s]) ? g_col[begs[s] + k + 1] : 0;
        // predicated feature loads + mins (uniform per 16-lane group)
        if (k < degs[0]) { float4 v = src4[col[0] * 16 + c4]; FMIN4(a0, v); }
        if (k < degs[1]) { float4 v = src4[col[1] * 16 + c4]; FMIN4(a1, v); }
        if (k < degs[2]) { float4 v = src4[col[2] * 16 + c4]; FMIN4(a2, v); }
        if (k < degs[3]) { float4 v = src4[col[3] * 16 + c4]; FMIN4(a3, v); }
#pragma unroll
        for (int s = 0; s < 4; s++) col[s] = ncol[s];
    }

    float4 sc, sh;
    if (bn) {
        sc = *(const float4*)&g_bnp[c4 * 4];
        sh = *(const float4*)&g_bnp[64 + c4 * 4];
    }
    float4 accs[4] = {a0, a1, a2, a3};
#pragma unroll
    for (int s = 0; s < 4; s++) {
        float4 m = accs[s];
        if (degs[s] == 0) m = make_float4(0.f, 0.f, 0.f, 0.f);
        else if (bn) {
            m.x = fmaxf(m.x * sc.x + sh.x, 0.f);
            m.y = fmaxf(m.y * sc.y + sh.y, 0.f);
            m.z = fmaxf(m.z * sc.z + sh.z, 0.f);
            m.w = fmaxf(m.w * sc.w + sh.w, 0.f);
        }
        int o = (s * 16 + sub) * 65 + 4 * c4;
        sX[o] = m.x; sX[o + 1] = m.y; sX[o + 2] = m.z; sX[o + 3] = m.w;
    }
}

// ---------------- fused layer: gather-min + dual-GEMM 64->64 + BN stats -----
#define MMA64() \
    _Pragma("unroll 4") \
    for (int ci = 0; ci < 64; ci++) { \
        ull bw0 = *(const ull*)&sW[ci * 64 + 2 * cg]; \
        ull bw1 = *(const ull*)&sW[ci * 64 + 2 * cg + 32]; \
        float x0 = sX[slot * 65 + ci]; \
        float x1 = sX[(slot + 16) * 65 + ci]; \
        float x2 = sX[(slot + 32) * 65 + ci]; \
        float x3 = sX[(slot + 48) * 65 + ci]; \
        ull a0, a1, a2, a3; \
        PACKF2(a0, x0, x0); PACKF2(a1, x1, x1); PACKF2(a2, x2, x2); PACKF2(a3, x3, x3); \
        FMA2(acc[0][0], a0, bw0, acc[0][0]); FMA2(acc[1][0], a0, bw1, acc[1][0]); \
        FMA2(acc[0][1], a1, bw0, acc[0][1]); FMA2(acc[1][1], a1, bw1, acc[1][1]); \
        FMA2(acc[0][2], a2, bw0, acc[0][2]); FMA2(acc[1][2], a2, bw1, acc[1][2]); \
        FMA2(acc[0][3], a3, bw0, acc[0][3]); FMA2(acc[1][3], a3, bw1, acc[1][3]); \
    }

__global__ void __launch_bounds__(256, 5)
layer64_kernel(const float* __restrict__ xin, int use_bn,
               const float* __restrict__ Wl,
               const float* __restrict__ Wr,
               const float* __restrict__ bias,
               const float* __restrict__ gam,
               const float* __restrict__ bet) {
    __shared__ __align__(16) float sW[64 * 64];
    __shared__ __align__(16) float sX[64 * 65];
    __shared__ bool amLast;
    float* sRS = sX;              // aliased: sX dead after last MMA
    float* sRQ = sX + 1024;

    int tid = threadIdx.x;
    int base = blockIdx.x * 64;
    const float* hsrc = use_bn ? (const float*)g_bufB : xin;
    float* dst = use_bn ? g_bufD : g_bufB;      // double buffer: never in-place
    const float4* src4 = (const float4*)hsrc;

    // Wl -> smem (float4)
    for (int q = tid; q < 1024; q += 256)
        ((float4*)sW)[q] = ((const float4*)Wl)[q];

    // ---- gather-min phase ----
    int c4 = tid & 15, sub = tid >> 4;
    gather4(src4, base, c4, sub, sX, use_bn != 0);
    __syncthreads();

    // ---- GEMM pass 1: Wl x agg ----
    int cg = c4, slot = sub;
    ull acc[2][4];
    {
        float2 bp0 = *(const float2*)&bias[2 * cg];
        float2 bp1 = *(const float2*)&bias[2 * cg + 32];
        ull b0, b1;
        PACKF2(b0, bp0.x, bp0.y);
        PACKF2(b1, bp1.x, bp1.y);
#pragma unroll
        for (int j = 0; j < 4; j++) { acc[0][j] = b0; acc[1][j] = b1; }
    }
    MMA64();
    __syncthreads();

    // ---- GEMM pass 2: Wr x h (BN+ReLU fused on load; float4) ----
    for (int q = tid; q < 1024; q += 256)
        ((float4*)sW)[q] = ((const float4*)Wr)[q];
    for (int q = tid; q < 1024; q += 256) {
        int nd = q >> 4, cq = q & 15, gn = base + nd;
        float4 v = make_float4(0.f, 0.f, 0.f, 0.f);
        if (gn < N_NODES) {
            v = src4[gn * 16 + cq];
            if (use_bn) {
                float4 bsc = *(const float4*)&g_bnp[cq * 4];
                float4 bsh = *(const float4*)&g_bnp[64 + cq * 4];
                v.x = fmaxf(v.x * bsc.x + bsh.x, 0.f);
                v.y = fmaxf(v.y * bsc.y + bsh.y, 0.f);
                v.z = fmaxf(v.z * bsc.z + bsh.z, 0.f);
                v.w = fmaxf(v.w * bsc.w + bsh.w, 0.f);
            }
        }
        int o = nd * 65 + 4 * cq;
        sX[o] = v.x; sX[o + 1] = v.y; sX[o + 2] = v.z; sX[o + 3] = v.w;
    }
    __syncthreads();
    MMA64();
    __syncthreads();   // sX reads done; safe to alias sRS/sRQ

    // ---- epilogue: store output pairs + BN partials ----
#pragma unroll
    for (int p = 0; p < 2; p++) {
        int co0 = 2 * cg + 32 * p;
        float s1l = 0.f, s2l = 0.f, s1h = 0.f, s2h = 0.f;
#pragma unroll
        for (int j = 0; j < 4; j++) {
            int gn = base + slot + 16 * j;
            float lo, hi;
            UNPACKF2(lo, hi, acc[p][j]);
            if (gn < N_NODES) {
                *(float2*)&dst[gn * C + co0] = make_float2(lo, hi);
                s1l += lo; s2l += lo * lo;
                s1h += hi; s2h += hi * hi;
            }
        }
        sRS[co0 * 16 + slot] = s1l;
        sRQ[co0 * 16 + slot] = s2l;
        sRS[(co0 + 1) * 16 + slot] = s1h;
        sRQ[(co0 + 1) * 16 + slot] = s2h;
    }
    __syncthreads();
    if (tid < 64) {
        float t1 = 0.0f, t2 = 0.0f;
#pragma unroll
        for (int s = 0; s < 16; s++) {
            t1 += sRS[tid * 16 + s];
            t2 += sRQ[tid * 16 + s];
        }
        g_partS[blockIdx.x * 64 + tid] = t1;
        g_partQ[blockIdx.x * 64 + tid] = t2;
    }
    __threadfence();
    __syncthreads();

    // ---- last block computes BN scale/shift (fixed-order, deterministic) ----
    if (tid == 0) amLast = (atomicAdd(&g_done, 1) == LTG - 1);
    __syncthreads();
    if (amLast) {
        __threadfence();
        int c = tid & 63, part = tid >> 6;
        float s = 0.0f, q = 0.0f;
        for (int i = part; i < LTG; i += 4) {
            s += g_partS[i * 64 + c];
            q += g_partQ[i * 64 + c];
        }
        sRS[tid] = s;
        sRQ[tid] = q;
        __syncthreads();
        if (tid < 64) {
            float S = sRS[tid] + sRS[tid + 64] + sRS[tid + 128] + sRS[tid + 192];
            float Q = sRQ[tid] + sRQ[tid + 64] + sRQ[tid + 128] + sRQ[tid + 192];
            float inv = 1.0f / (float)N_NODES;
            float mu = S * inv;
            float var = Q * inv - mu * mu;
            float scale = gam[tid] * rsqrtf(var + BN_EPS);
            g_bnp[tid] = scale;
            g_bnp[64 + tid] = bet[tid] - mu * scale;
        }
        if (tid == 0) g_done = 0;   // ready for next layer / replay
    }
}

// ---------------- fused layer 3: gather-min + dual-GEMM 64->16 + log_softmax
__global__ void __launch_bounds__(256, 5)
layer16_kernel(const float* __restrict__ Wl,
               const float* __restrict__ Wr,
               const float* __restrict__ b,
               float* __restrict__ out) {
    __shared__ float sWl[64 * 16], sWr[64 * 16];
    __shared__ __align__(16) float sA[64 * 65];
    __shared__ __align__(16) float sH[64 * 65];

    int tid = threadIdx.x;
    int base = blockIdx.x * 64;
    const float4* src4 = (const float4*)g_bufD;   // layer-2 output buffer

    for (int q = tid; q < 1024; q += 256) { sWl[q] = Wl[q]; sWr[q] = Wr[q]; }

    // gather-min of h2 rows (bn2+relu post-min, monotone) into sA
    int c4 = tid & 15, sub = tid >> 4;
    gather4(src4, base, c4, sub, sA, true);

    // h2 rows (contiguous, float4) with bn2+relu into sH
    for (int q = tid; q < 1024; q += 256) {
        int nd = q >> 4, cq = q & 15, gn = base + nd;
        float4 v = make_float4(0.f, 0.f, 0.f, 0.f);
        if (gn < N_NODES) {
            v = src4[gn * 16 + cq];
            float4 bsc = *(const float4*)&g_bnp[cq * 4];
            float4 bsh = *(const float4*)&g_bnp[64 + cq * 4];
            v.x = fmaxf(v.x * bsc.x + bsh.x, 0.f);
            v.y = fmaxf(v.y * bsc.y + bsh.y, 0.f);
            v.z = fmaxf(v.z * bsc.z + bsh.z, 0.f);
            v.w = fmaxf(v.w * bsc.w + bsh.w, 0.f);
        }
        int o = nd * 65 + 4 * cq;
        sH[o] = v.x; sH[o + 1] = v.y; sH[o + 2] = v.z; sH[o + 3] = v.w;
    }
    __syncthreads();

    int c_out = tid & 15, nslot = tid >> 4;
    float acc[4];
    float bb = b[c_out];
#pragma unroll
    for (int j = 0; j < 4; j++) acc[j] = bb;

#pragma unroll 8
    for (int ci = 0; ci < 64; ci++) {
        float wl = sWl[ci * 16 + c_out];
        float wr = sWr[ci * 16 + c_out];
#pragma unroll
        for (int j = 0; j < 4; j++) {
            int nd = nslot + 16 * j;
            acc[j] += sA[nd * 65 + ci] * wl + sH[nd * 65 + ci] * wr;
        }
    }

    // log_softmax: 16 channels of a node live in 16 consecutive lanes.
#pragma unroll
    for (int j = 0; j < 4; j++) {
        int gn = base + nslot + 16 * j;
        float v = acc[j];
        float m = v;
#pragma unroll
        for (int off = 8; off; off >>= 1)
            m = fmaxf(m, __shfl_xor_sync(0xffffffffu, m, off));
        float e = expf(v - m);
        float s = e;
#pragma unroll
        for (int off = 8; off; off >>= 1)
            s += __shfl_xor_sync(0xffffffffu, s, off);
        if (gn < N_NODES) out[gn * OUTC + c_out] = v - m - logf(s);
    }
}

// ---------------- launch: 6 kernel launches ----------------
extern "C" void kernel_launch(void* const* d_in, const int* in_sizes, int n_in,
                              void* d_out, int out_size) {
    const float* x   = (const float*)d_in[0];
    const int*   ei  = (const int*)d_in[1];   // int32 (JAX x64 disabled)
    const float* W1l = (const float*)d_in[2];
    const float* b1  = (const float*)d_in[3];
    const float* W1r = (const float*)d_in[4];
    const float* g1  = (const float*)d_in[5];
    const float* be1 = (const float*)d_in[6];
    const float* W2l = (const float*)d_in[7];
    const float* b2  = (const float*)d_in[8];
    const float* W2r = (const float*)d_in[9];
    const float* g2  = (const float*)d_in[10];
    const float* be2 = (const float*)d_in[11];
    const float* W3l = (const float*)d_in[12];
    const float* b3  = (const float*)d_in[13];
    const float* W3r = (const float*)d_in[14];
    float* out = (float*)d_out;

    hist_kernel<<<E4G, 256>>>(ei);
    offsets_kernel<<<NG, 256>>>();
    scatter_kernel<<<E4G, 256>>>(ei);

    layer64_kernel<<<LTG, 256>>>(x, 0, W1l, W1r, b1, g1, be1);
    layer64_kernel<<<LTG, 256>>>(x, 1, W2l, W2r, b2, g2, be2);
    layer16_kernel<<<LTG, 256>>>(W3l, W3r, b3, out);
}